// round 1
// baseline (speedup 1.0000x reference)
#include <cuda_runtime.h>
#include <math.h>

// Problem constants
#define BATCH 4
#define SEQ   2048
#define DIM   1024
#define NH    16
#define HD    64
#define NR    (BATCH * SEQ)        // 8192 rows
#define QK_SCALE 0.125f            // 1/sqrt(64)

// Scratch (allocation-free: __device__ globals)
__device__ float g_Q[(size_t)BATCH * NH * SEQ * HD];
__device__ float g_K[(size_t)BATCH * NH * SEQ * HD];
__device__ float g_V[(size_t)BATCH * NH * SEQ * HD];
__device__ float g_C[(size_t)NR * DIM];

// ---------------------------------------------------------------------------
// GEMM: out[n,m] = sum_k A[n,k] * W[m,k] + bias[m]
// A: [NR, DIM] row-major. W: [DIM, DIM] row-major (out-dim major, K inner).
// mode 0: scatter into [B,H,S,DK] layout (QKV projections)
// mode 1: plain row-major [NR, DIM] (context/output projection)
// Block: 128x128 tile, BK=16, 256 threads, 8x8 microtile.
// ---------------------------------------------------------------------------
__global__ __launch_bounds__(256, 2)
void gemm128(const float* __restrict__ A, const float* __restrict__ W,
             const float* __restrict__ bias, float* __restrict__ out, int mode)
{
    __shared__ float sA[16][132];   // transposed: sA[kk][row], pad 4 keeps 16B align
    __shared__ float sW[16][132];

    const int tid = threadIdx.x;
    const int tx = tid & 15;        // 16 col-groups
    const int ty = tid >> 4;        // 16 row-groups
    const int n0 = blockIdx.y << 7;
    const int m0 = blockIdx.x << 7;

    float acc[8][8];
#pragma unroll
    for (int i = 0; i < 8; i++)
#pragma unroll
        for (int j = 0; j < 8; j++) acc[i][j] = 0.f;

    for (int k0 = 0; k0 < DIM; k0 += 16) {
        // Load 128x16 tiles of A and W (transposed into smem).
#pragma unroll
        for (int t = 0; t < 2; t++) {
            int idx = tid + (t << 8);           // 0..511
            int row = idx >> 2;                 // 0..127
            int c4  = (idx & 3) << 2;           // 0,4,8,12
            float4 av = *(const float4*)&A[(size_t)(n0 + row) * DIM + k0 + c4];
            sA[c4 + 0][row] = av.x; sA[c4 + 1][row] = av.y;
            sA[c4 + 2][row] = av.z; sA[c4 + 3][row] = av.w;
            float4 wv = *(const float4*)&W[(size_t)(m0 + row) * DIM + k0 + c4];
            sW[c4 + 0][row] = wv.x; sW[c4 + 1][row] = wv.y;
            sW[c4 + 2][row] = wv.z; sW[c4 + 3][row] = wv.w;
        }
        __syncthreads();

#pragma unroll
        for (int kk = 0; kk < 16; kk++) {
            float a[8], w[8];
            float4 a0 = *(const float4*)&sA[kk][(ty << 3) + 0];
            float4 a1 = *(const float4*)&sA[kk][(ty << 3) + 4];
            a[0]=a0.x; a[1]=a0.y; a[2]=a0.z; a[3]=a0.w;
            a[4]=a1.x; a[5]=a1.y; a[6]=a1.z; a[7]=a1.w;
            float4 w0 = *(const float4*)&sW[kk][(tx << 3) + 0];
            float4 w1 = *(const float4*)&sW[kk][(tx << 3) + 4];
            w[0]=w0.x; w[1]=w0.y; w[2]=w0.z; w[3]=w0.w;
            w[4]=w1.x; w[5]=w1.y; w[6]=w1.z; w[7]=w1.w;
#pragma unroll
            for (int i = 0; i < 8; i++)
#pragma unroll
                for (int j = 0; j < 8; j++)
                    acc[i][j] += a[i] * w[j];
        }
        __syncthreads();
    }

    // Epilogue
#pragma unroll
    for (int i = 0; i < 8; i++) {
        const int n = n0 + (ty << 3) + i;
#pragma unroll
        for (int j = 0; j < 8; j++) {
            const int m = m0 + (tx << 3) + j;
            float v = acc[i][j] + bias[m];
            if (mode == 0) {
                const int bi = n / SEQ, s = n % SEQ;
                const int h = m >> 6, dk = m & 63;
                out[(((size_t)bi * NH + h) * SEQ + s) * HD + dk] = v;
            } else {
                out[(size_t)n * DIM + m] = v;
            }
        }
    }
}

// ---------------------------------------------------------------------------
// Causal flash attention, fp32, online softmax.
// Q/K/V: [B*H, S, HD]. Output C: [B, S, D] (head-interleaved for O-proj).
// Block: one 64-query tile of one (b,h). 256 threads = 16x16, 4x4 microtile.
// smem: sQT (Q transposed), sKP (K transposed, reused for P), sV (natural).
// ---------------------------------------------------------------------------
__global__ __launch_bounds__(256)
void flash_attn(const float* __restrict__ Q, const float* __restrict__ K,
                const float* __restrict__ V, float* __restrict__ C)
{
    __shared__ float sQT[64][64];   // [dk][qrow]
    __shared__ float sKP[64][64];   // K: [dk][krow]; later P: [qrow][kcol]
    __shared__ float sV [64][64];   // [krow][dk]

    const int tid = threadIdx.x;
    const int tx = tid & 15;        // k-tile col group (4 cols)
    const int ty = tid >> 4;        // q row group (4 rows)
    const int qt = blockIdx.x;      // query tile index
    const int bh = blockIdx.y;      // b*NH + h
    const int q0 = qt << 6;

    const float* Qb = Q + (size_t)bh * SEQ * HD;
    const float* Kb = K + (size_t)bh * SEQ * HD;
    const float* Vb = V + (size_t)bh * SEQ * HD;

    // Load Q tile transposed: sQT[dk][qrow]
    for (int idx = tid; idx < 64 * 16; idx += 256) {
        int r  = idx & 63;                 // q row in tile
        int c4 = (idx >> 6) << 2;          // dk 0,4,...,60
        float4 qv = *(const float4*)&Qb[(size_t)(q0 + r) * HD + c4];
        sQT[c4 + 0][r] = qv.x; sQT[c4 + 1][r] = qv.y;
        sQT[c4 + 2][r] = qv.z; sQT[c4 + 3][r] = qv.w;
    }

    float m_i[4], l_i[4], o[4][4];
#pragma unroll
    for (int i = 0; i < 4; i++) {
        m_i[i] = -INFINITY; l_i[i] = 0.f;
#pragma unroll
        for (int j = 0; j < 4; j++) o[i][j] = 0.f;
    }

    for (int jt = 0; jt <= qt; jt++) {
        const int k0 = jt << 6;
        __syncthreads();   // previous iter's P / V reads done

        // Load K transposed + V natural
        for (int idx = tid; idx < 64 * 16; idx += 256) {
            int r  = idx & 63;
            int c4 = (idx >> 6) << 2;
            float4 kv = *(const float4*)&Kb[(size_t)(k0 + r) * HD + c4];
            sKP[c4 + 0][r] = kv.x; sKP[c4 + 1][r] = kv.y;
            sKP[c4 + 2][r] = kv.z; sKP[c4 + 3][r] = kv.w;
            *(float4*)&sV[r][c4] = *(const float4*)&Vb[(size_t)(k0 + r) * HD + c4];
        }
        __syncthreads();

        // S = Q K^T (4x4 per thread)
        float sc[4][4];
#pragma unroll
        for (int i = 0; i < 4; i++)
#pragma unroll
            for (int j = 0; j < 4; j++) sc[i][j] = 0.f;

#pragma unroll 8
        for (int kk = 0; kk < 64; kk++) {
            float4 av = *(const float4*)&sQT[kk][ty << 2];
            float4 bv = *(const float4*)&sKP[kk][tx << 2];
            float a[4] = {av.x, av.y, av.z, av.w};
            float b[4] = {bv.x, bv.y, bv.z, bv.w};
#pragma unroll
            for (int i = 0; i < 4; i++)
#pragma unroll
                for (int j = 0; j < 4; j++)
                    sc[i][j] += a[i] * b[j];
        }

        // scale + causal mask on the diagonal tile
        const bool diag = (jt == qt);
#pragma unroll
        for (int i = 0; i < 4; i++)
#pragma unroll
            for (int j = 0; j < 4; j++) {
                float v = sc[i][j] * QK_SCALE;
                if (diag && ((tx << 2) + j > (ty << 2) + i)) v = -INFINITY;
                sc[i][j] = v;
            }

        // online softmax update (row reductions across tx within half-warp)
        float alpha[4];
#pragma unroll
        for (int i = 0; i < 4; i++) {
            float rm = fmaxf(fmaxf(sc[i][0], sc[i][1]), fmaxf(sc[i][2], sc[i][3]));
#pragma unroll
            for (int off = 8; off > 0; off >>= 1)
                rm = fmaxf(rm, __shfl_xor_sync(0xffffffffu, rm, off, 16));
            float mn = fmaxf(m_i[i], rm);
            alpha[i] = __expf(m_i[i] - mn);
            m_i[i] = mn;
            float rs = 0.f;
#pragma unroll
            for (int j = 0; j < 4; j++) {
                sc[i][j] = __expf(sc[i][j] - mn);
                rs += sc[i][j];
            }
#pragma unroll
            for (int off = 8; off > 0; off >>= 1)
                rs += __shfl_xor_sync(0xffffffffu, rs, off, 16);
            l_i[i] = l_i[i] * alpha[i] + rs;
#pragma unroll
            for (int j = 0; j < 4; j++) o[i][j] *= alpha[i];
        }

        // Stage P into sKP (K reads complete)
        __syncthreads();
#pragma unroll
        for (int i = 0; i < 4; i++) {
            float4 pv = {sc[i][0], sc[i][1], sc[i][2], sc[i][3]};
            *(float4*)&sKP[(ty << 2) + i][tx << 2] = pv;
        }
        __syncthreads();

        // O += P V
#pragma unroll 8
        for (int kk = 0; kk < 64; kk++) {
            float p[4];
#pragma unroll
            for (int i = 0; i < 4; i++) p[i] = sKP[(ty << 2) + i][kk];
            float4 vv = *(const float4*)&sV[kk][tx << 2];
            float v[4] = {vv.x, vv.y, vv.z, vv.w};
#pragma unroll
            for (int i = 0; i < 4; i++)
#pragma unroll
                for (int j = 0; j < 4; j++)
                    o[i][j] += p[i] * v[j];
        }
    }

    // Epilogue: C[b, s, h*HD + dk] = o / l
    const int bi = bh >> 4;
    const int h  = bh & 15;
#pragma unroll
    for (int i = 0; i < 4; i++) {
        const float inv = 1.f / l_i[i];
        const int sq = q0 + (ty << 2) + i;
        float4 r;
        r.x = o[i][0] * inv; r.y = o[i][1] * inv;
        r.z = o[i][2] * inv; r.w = o[i][3] * inv;
        *(float4*)&C[((size_t)bi * SEQ + sq) * DIM + h * HD + (tx << 2)] = r;
    }
}

// ---------------------------------------------------------------------------
// Launch
// ---------------------------------------------------------------------------
extern "C" void kernel_launch(void* const* d_in, const int* in_sizes, int n_in,
                              void* d_out, int out_size)
{
    (void)in_sizes; (void)n_in; (void)out_size;
    const float* x  = (const float*)d_in[0];
    // d_in[1] is the causal mask (int32) — causality applied analytically.
    const float* Wq = (const float*)d_in[2];
    const float* bq = (const float*)d_in[3];
    const float* Wk = (const float*)d_in[4];
    const float* bk = (const float*)d_in[5];
    const float* Wv = (const float*)d_in[6];
    const float* bv = (const float*)d_in[7];
    const float* Wo = (const float*)d_in[8];
    const float* bo = (const float*)d_in[9];
    float* out = (float*)d_out;

    float *Qp, *Kp, *Vp, *Cp;
    cudaGetSymbolAddress((void**)&Qp, g_Q);
    cudaGetSymbolAddress((void**)&Kp, g_K);
    cudaGetSymbolAddress((void**)&Vp, g_V);
    cudaGetSymbolAddress((void**)&Cp, g_C);

    dim3 gemm_grid(DIM / 128, NR / 128);   // 8 x 64
    gemm128<<<gemm_grid, 256>>>(x, Wq, bq, Qp, 0);
    gemm128<<<gemm_grid, 256>>>(x, Wk, bk, Kp, 0);
    gemm128<<<gemm_grid, 256>>>(x, Wv, bv, Vp, 0);

    dim3 attn_grid(SEQ / 64, BATCH * NH);  // 32 x 64
    flash_attn<<<attn_grid, 256>>>(Qp, Kp, Vp, Cp);

    gemm128<<<gemm_grid, 256>>>(Cp, Wo, bo, out, 1);
}

// round 3
// speedup vs baseline: 1.4633x; 1.4633x over previous
#include <cuda_runtime.h>
#include <cuda_bf16.h>
#include <math.h>
#include <stdint.h>

// Problem constants
#define BATCH 4
#define SEQ   2048
#define DIM   1024
#define NH    16
#define HD    64
#define NR    (BATCH * SEQ)        // 8192 rows
#define QK_SCALE 0.125f            // 1/sqrt(64)

// Scratch (allocation-free: __device__ globals)
__device__ float g_Q[(size_t)BATCH * NH * SEQ * HD];
__device__ float g_K[(size_t)BATCH * NH * SEQ * HD];
__device__ float g_V[(size_t)BATCH * NH * SEQ * HD];
__device__ float g_C[(size_t)NR * DIM];

// ===========================================================================
// Helpers
// ===========================================================================
__device__ __forceinline__ uint32_t smem_u32(const void* p) {
    uint32_t a;
    asm("{ .reg .u64 t; cvta.to.shared.u64 t, %1; cvt.u32.u64 %0, t; }"
        : "=r"(a) : "l"(p));
    return a;
}

__device__ __forceinline__ uint32_t pack_bf16x2(float a, float b) {
    __nv_bfloat162 t = __floats2bfloat162_rn(a, b);
    return *reinterpret_cast<uint32_t*>(&t);
}

#define LDMX4(r, addr) \
    asm volatile("ldmatrix.sync.aligned.m8n8.x4.shared.b16 {%0,%1,%2,%3}, [%4];" \
        : "=r"((r)[0]), "=r"((r)[1]), "=r"((r)[2]), "=r"((r)[3]) : "r"(addr))

#define MMA_BF16(d, a, b0, b1) \
    asm volatile("mma.sync.aligned.m16n8k16.row.col.f32.bf16.bf16.f32 " \
        "{%0,%1,%2,%3}, {%4,%5,%6,%7}, {%8,%9}, {%0,%1,%2,%3};" \
        : "+f"((d)[0]), "+f"((d)[1]), "+f"((d)[2]), "+f"((d)[3]) \
        : "r"((a)[0]), "r"((a)[1]), "r"((a)[2]), "r"((a)[3]), "r"(b0), "r"(b1))

// bf16 tile in smem: logical [128 rows][32 k]. Two logical rows share one
// 128-byte physical row; SW128 XOR swizzle keeps ldmatrix conflict-free and
// every row address 16B-aligned.
// byte layout: prow = r>>1 (0..63), chunk = (r&1)*4 + bytecol/16,
//              phys = prow*128 + ((chunk ^ (prow&7))*16) + (bytecol&15)
__device__ __forceinline__ uint32_t sw_off(int r, int bytecol) {
    int prow  = r >> 1;
    int chunk = ((r & 1) << 2) | (bytecol >> 4);
    return (uint32_t)(prow * 128 + ((chunk ^ (prow & 7)) << 4) + (bytecol & 15));
}

// ===========================================================================
// Tensor-core GEMM via mma.sync (bf16x3 fp32 emulation).
// out[n,m] = sum_k A[n,k] * W[m,k] + bias[m]
// Tile 128x128, BK=32, double-buffered smem, 256 threads.
// Warps: 4 in M x 2 in N; warp tile 32x64 (2 m16 x 8 n8).
// mode 0: scatter into [B,H,S,DK]; mode 1: row-major [NR,DIM].
// ===========================================================================
#define GBK        32
#define GTILE      8192                   // 64 prow * 128 B (one bf16 matrix tile)
#define GBUF       (4 * GTILE)            // Ah, Al, Wh, Wl
#define GSMEM_TOT  (2 * GBUF)             // 65536 bytes

__global__ __launch_bounds__(256, 1)
void gemm_mma(const float* __restrict__ A, const float* __restrict__ W,
              const float* __restrict__ bias, float* __restrict__ out, int mode)
{
    extern __shared__ char smem[];
    const uint32_t sb = smem_u32(smem);
    const int tid  = threadIdx.x;
    const int wid  = tid >> 5;
    const int lane = tid & 31;
    const int wm = wid & 3;          // warp M index (0..3)
    const int wn = wid >> 2;         // warp N index (0..1)
    const int n0 = blockIdx.y << 7;  // A-row block
    const int m0 = blockIdx.x << 7;  // W-row block

    float acc[2][8][4];
#pragma unroll
    for (int mt = 0; mt < 2; mt++)
#pragma unroll
        for (int nt = 0; nt < 8; nt++)
#pragma unroll
            for (int j = 0; j < 4; j++) acc[mt][nt][j] = 0.f;

    float4 ar[4], wr[4];

    // ---- G2R: load one 128x32 fp32 chunk of A and W into registers
    auto G2R = [&](int c) {
        const int k0 = c << 5;
#pragma unroll
        for (int i = 0; i < 4; i++) {
            const int idx = (i << 8) + tid;       // 0..1023
            const int row = idx >> 3;             // 0..127
            const int cg  = (idx & 7) << 2;       // 0,4,...,28
            ar[i] = *(const float4*)&A[(size_t)(n0 + row) * DIM + k0 + cg];
            wr[i] = *(const float4*)&W[(size_t)(m0 + row) * DIM + k0 + cg];
        }
    };

    // ---- R2S: split fp32 -> bf16 hi/lo, store swizzled into buffer b
    auto R2S = [&](int b) {
        char* buf = smem + b * GBUF;
#pragma unroll
        for (int i = 0; i < 4; i++) {
            const int idx = (i << 8) + tid;
            const int row = idx >> 3;
            const int bytecol = (idx & 7) << 3;   // 0,8,...,56
            const uint32_t so = sw_off(row, bytecol);

            float4 av = ar[i], wv = wr[i];
            float ah0 = __bfloat162float(__float2bfloat16_rn(av.x));
            float ah1 = __bfloat162float(__float2bfloat16_rn(av.y));
            float ah2 = __bfloat162float(__float2bfloat16_rn(av.z));
            float ah3 = __bfloat162float(__float2bfloat16_rn(av.w));
            uint2 ahp = make_uint2(pack_bf16x2(ah0, ah1), pack_bf16x2(ah2, ah3));
            uint2 alp = make_uint2(pack_bf16x2(av.x - ah0, av.y - ah1),
                                   pack_bf16x2(av.z - ah2, av.w - ah3));
            float wh0 = __bfloat162float(__float2bfloat16_rn(wv.x));
            float wh1 = __bfloat162float(__float2bfloat16_rn(wv.y));
            float wh2 = __bfloat162float(__float2bfloat16_rn(wv.z));
            float wh3 = __bfloat162float(__float2bfloat16_rn(wv.w));
            uint2 whp = make_uint2(pack_bf16x2(wh0, wh1), pack_bf16x2(wh2, wh3));
            uint2 wlp = make_uint2(pack_bf16x2(wv.x - wh0, wv.y - wh1),
                                   pack_bf16x2(wv.z - wh2, wv.w - wh3));

            *(uint2*)(buf + 0 * GTILE + so) = ahp;
            *(uint2*)(buf + 1 * GTILE + so) = alp;
            *(uint2*)(buf + 2 * GTILE + so) = whp;
            *(uint2*)(buf + 3 * GTILE + so) = wlp;
        }
    };

    // ---- compute: consume buffer b (2 k16 steps, 3 bf16x3 passes)
    auto compute = [&](int b) {
        const uint32_t buf = sb + b * GBUF;
#pragma unroll
        for (int ks = 0; ks < 2; ks++) {
            uint32_t a_h[2][4], a_l[2][4], b_h[4][4], b_l[4][4];
#pragma unroll
            for (int mt = 0; mt < 2; mt++) {
                const int r  = wm * 32 + mt * 16 + (lane & 15);
                const int bc = ks * 32 + ((lane >> 4) & 1) * 16;
                const uint32_t o = sw_off(r, bc);
                LDMX4(a_h[mt], buf + 0 * GTILE + o);
                LDMX4(a_l[mt], buf + 1 * GTILE + o);
            }
#pragma unroll
            for (int bt = 0; bt < 4; bt++) {
                const int rn = wn * 64 + bt * 16 + ((lane >> 4) << 3) + (lane & 7);
                const int bc = ks * 32 + ((lane >> 3) & 1) * 16;
                const uint32_t o = sw_off(rn, bc);
                LDMX4(b_h[bt], buf + 2 * GTILE + o);
                LDMX4(b_l[bt], buf + 3 * GTILE + o);
            }
#pragma unroll
            for (int mt = 0; mt < 2; mt++)
#pragma unroll
                for (int nt = 0; nt < 8; nt++)
                    MMA_BF16(acc[mt][nt], a_h[mt],
                             b_h[nt >> 1][(nt & 1) << 1], b_h[nt >> 1][((nt & 1) << 1) + 1]);
#pragma unroll
            for (int mt = 0; mt < 2; mt++)
#pragma unroll
                for (int nt = 0; nt < 8; nt++)
                    MMA_BF16(acc[mt][nt], a_h[mt],
                             b_l[nt >> 1][(nt & 1) << 1], b_l[nt >> 1][((nt & 1) << 1) + 1]);
#pragma unroll
            for (int mt = 0; mt < 2; mt++)
#pragma unroll
                for (int nt = 0; nt < 8; nt++)
                    MMA_BF16(acc[mt][nt], a_l[mt],
                             b_h[nt >> 1][(nt & 1) << 1], b_h[nt >> 1][((nt & 1) << 1) + 1]);
        }
    };

    // ---- pipelined main loop
    G2R(0); R2S(0); __syncthreads();
    for (int c = 0; c < DIM / GBK; c++) {
        if (c < DIM / GBK - 1) G2R(c + 1);
        compute(c & 1);
        if (c < DIM / GBK - 1) { R2S((c + 1) & 1); __syncthreads(); }
    }

    // ---- epilogue: direct stores with bias (+ optional QKV scatter)
#pragma unroll
    for (int mt = 0; mt < 2; mt++) {
        const int r0 = n0 + wm * 32 + mt * 16 + (lane >> 2);
#pragma unroll
        for (int nt = 0; nt < 8; nt++) {
            const int m = m0 + wn * 64 + nt * 8 + ((lane & 3) << 1);
            const float2 bv = *(const float2*)&bias[m];
            float2 v0 = make_float2(acc[mt][nt][0] + bv.x, acc[mt][nt][1] + bv.y);
            float2 v1 = make_float2(acc[mt][nt][2] + bv.x, acc[mt][nt][3] + bv.y);
            if (mode == 0) {
                const int h = m >> 6, dk = m & 63;
                {
                    const int n = r0, bi = n >> 11, s = n & 2047;
                    *(float2*)&out[(((size_t)bi * NH + h) * SEQ + s) * HD + dk] = v0;
                }
                {
                    const int n = r0 + 8, bi = n >> 11, s = n & 2047;
                    *(float2*)&out[(((size_t)bi * NH + h) * SEQ + s) * HD + dk] = v1;
                }
            } else {
                *(float2*)&out[(size_t)r0 * DIM + m] = v0;
                *(float2*)&out[(size_t)(r0 + 8) * DIM + m] = v1;
            }
        }
    }
}

// ---------------------------------------------------------------------------
// Causal flash attention, fp32, online softmax (unchanged from R1).
// ---------------------------------------------------------------------------
__global__ __launch_bounds__(256)
void flash_attn(const float* __restrict__ Q, const float* __restrict__ K,
                const float* __restrict__ V, float* __restrict__ C)
{
    __shared__ float sQT[64][64];
    __shared__ float sKP[64][64];
    __shared__ float sV [64][64];

    const int tid = threadIdx.x;
    const int tx = tid & 15;
    const int ty = tid >> 4;
    const int qt = blockIdx.x;
    const int bh = blockIdx.y;
    const int q0 = qt << 6;

    const float* Qb = Q + (size_t)bh * SEQ * HD;
    const float* Kb = K + (size_t)bh * SEQ * HD;
    const float* Vb = V + (size_t)bh * SEQ * HD;

    for (int idx = tid; idx < 64 * 16; idx += 256) {
        int r  = idx & 63;
        int c4 = (idx >> 6) << 2;
        float4 qv = *(const float4*)&Qb[(size_t)(q0 + r) * HD + c4];
        sQT[c4 + 0][r] = qv.x; sQT[c4 + 1][r] = qv.y;
        sQT[c4 + 2][r] = qv.z; sQT[c4 + 3][r] = qv.w;
    }

    float m_i[4], l_i[4], o[4][4];
#pragma unroll
    for (int i = 0; i < 4; i++) {
        m_i[i] = -INFINITY; l_i[i] = 0.f;
#pragma unroll
        for (int j = 0; j < 4; j++) o[i][j] = 0.f;
    }

    for (int jt = 0; jt <= qt; jt++) {
        const int k0 = jt << 6;
        __syncthreads();

        for (int idx = tid; idx < 64 * 16; idx += 256) {
            int r  = idx & 63;
            int c4 = (idx >> 6) << 2;
            float4 kv = *(const float4*)&Kb[(size_t)(k0 + r) * HD + c4];
            sKP[c4 + 0][r] = kv.x; sKP[c4 + 1][r] = kv.y;
            sKP[c4 + 2][r] = kv.z; sKP[c4 + 3][r] = kv.w;
            *(float4*)&sV[r][c4] = *(const float4*)&Vb[(size_t)(k0 + r) * HD + c4];
        }
        __syncthreads();

        float sc[4][4];
#pragma unroll
        for (int i = 0; i < 4; i++)
#pragma unroll
            for (int j = 0; j < 4; j++) sc[i][j] = 0.f;

#pragma unroll 8
        for (int kk = 0; kk < 64; kk++) {
            float4 av = *(const float4*)&sQT[kk][ty << 2];
            float4 bv = *(const float4*)&sKP[kk][tx << 2];
            float a[4] = {av.x, av.y, av.z, av.w};
            float b[4] = {bv.x, bv.y, bv.z, bv.w};
#pragma unroll
            for (int i = 0; i < 4; i++)
#pragma unroll
                for (int j = 0; j < 4; j++)
                    sc[i][j] += a[i] * b[j];
        }

        const bool diag = (jt == qt);
#pragma unroll
        for (int i = 0; i < 4; i++)
#pragma unroll
            for (int j = 0; j < 4; j++) {
                float v = sc[i][j] * QK_SCALE;
                if (diag && ((tx << 2) + j > (ty << 2) + i)) v = -INFINITY;
                sc[i][j] = v;
            }

        float alpha[4];
#pragma unroll
        for (int i = 0; i < 4; i++) {
            float rm = fmaxf(fmaxf(sc[i][0], sc[i][1]), fmaxf(sc[i][2], sc[i][3]));
#pragma unroll
            for (int off = 8; off > 0; off >>= 1)
                rm = fmaxf(rm, __shfl_xor_sync(0xffffffffu, rm, off, 16));
            float mn = fmaxf(m_i[i], rm);
            alpha[i] = __expf(m_i[i] - mn);
            m_i[i] = mn;
            float rs = 0.f;
#pragma unroll
            for (int j = 0; j < 4; j++) {
                sc[i][j] = __expf(sc[i][j] - mn);
                rs += sc[i][j];
            }
#pragma unroll
            for (int off = 8; off > 0; off >>= 1)
                rs += __shfl_xor_sync(0xffffffffu, rs, off, 16);
            l_i[i] = l_i[i] * alpha[i] + rs;
#pragma unroll
            for (int j = 0; j < 4; j++) o[i][j] *= alpha[i];
        }

        __syncthreads();
#pragma unroll
        for (int i = 0; i < 4; i++) {
            float4 pv = {sc[i][0], sc[i][1], sc[i][2], sc[i][3]};
            *(float4*)&sKP[(ty << 2) + i][tx << 2] = pv;
        }
        __syncthreads();

#pragma unroll 8
        for (int kk = 0; kk < 64; kk++) {
            float p[4];
#pragma unroll
            for (int i = 0; i < 4; i++) p[i] = sKP[(ty << 2) + i][kk];
            float4 vv = *(const float4*)&sV[kk][tx << 2];
            float v[4] = {vv.x, vv.y, vv.z, vv.w};
#pragma unroll
            for (int i = 0; i < 4; i++)
#pragma unroll
                for (int j = 0; j < 4; j++)
                    o[i][j] += p[i] * v[j];
        }
    }

    const int bi = bh >> 4;
    const int h  = bh & 15;
#pragma unroll
    for (int i = 0; i < 4; i++) {
        const float inv = 1.f / l_i[i];
        const int sq = q0 + (ty << 2) + i;
        float4 r;
        r.x = o[i][0] * inv; r.y = o[i][1] * inv;
        r.z = o[i][2] * inv; r.w = o[i][3] * inv;
        *(float4*)&C[((size_t)bi * SEQ + sq) * DIM + h * HD + (tx << 2)] = r;
    }
}

// ---------------------------------------------------------------------------
// Launch
// ---------------------------------------------------------------------------
extern "C" void kernel_launch(void* const* d_in, const int* in_sizes, int n_in,
                              void* d_out, int out_size)
{
    (void)in_sizes; (void)n_in; (void)out_size;
    const float* x  = (const float*)d_in[0];
    const float* Wq = (const float*)d_in[2];
    const float* bq = (const float*)d_in[3];
    const float* Wk = (const float*)d_in[4];
    const float* bk = (const float*)d_in[5];
    const float* Wv = (const float*)d_in[6];
    const float* bv = (const float*)d_in[7];
    const float* Wo = (const float*)d_in[8];
    const float* bo = (const float*)d_in[9];
    float* out = (float*)d_out;

    float *Qp, *Kp, *Vp, *Cp;
    cudaGetSymbolAddress((void**)&Qp, g_Q);
    cudaGetSymbolAddress((void**)&Kp, g_K);
    cudaGetSymbolAddress((void**)&Vp, g_V);
    cudaGetSymbolAddress((void**)&Cp, g_C);

    cudaFuncSetAttribute(gemm_mma, cudaFuncAttributeMaxDynamicSharedMemorySize,
                         GSMEM_TOT);

    dim3 gemm_grid(DIM / 128, NR / 128);   // 8 x 64
    gemm_mma<<<gemm_grid, 256, GSMEM_TOT>>>(x, Wq, bq, Qp, 0);
    gemm_mma<<<gemm_grid, 256, GSMEM_TOT>>>(x, Wk, bk, Kp, 0);
    gemm_mma<<<gemm_grid, 256, GSMEM_TOT>>>(x, Wv, bv, Vp, 0);

    dim3 attn_grid(SEQ / 64, BATCH * NH);  // 32 x 64
    flash_attn<<<attn_grid, 256>>>(Qp, Kp, Vp, Cp);

    gemm_mma<<<gemm_grid, 256, GSMEM_TOT>>>(Cp, Wo, bo, out, 1);
}

// round 4
// speedup vs baseline: 2.7130x; 1.8541x over previous
#include <cuda_runtime.h>
#include <cuda_bf16.h>
#include <math.h>
#include <stdint.h>

// Problem constants
#define BATCH 4
#define SEQ   2048
#define DIM   1024
#define NH    16
#define HD    64
#define NR    (BATCH * SEQ)        // 8192 rows
#define QK_SCALE 0.125f            // 1/sqrt(64)

// Scratch (allocation-free: __device__ globals)
__device__ float g_Q[(size_t)BATCH * NH * SEQ * HD];
__device__ float g_K[(size_t)BATCH * NH * SEQ * HD];
__device__ float g_V[(size_t)BATCH * NH * SEQ * HD];
__device__ float g_C[(size_t)NR * DIM];

// ===========================================================================
// Helpers
// ===========================================================================
__device__ __forceinline__ uint32_t smem_u32(const void* p) {
    uint32_t a;
    asm("{ .reg .u64 t; cvta.to.shared.u64 t, %1; cvt.u32.u64 %0, t; }"
        : "=r"(a) : "l"(p));
    return a;
}

__device__ __forceinline__ uint32_t pack_bf16x2(float a, float b) {
    __nv_bfloat162 t = __floats2bfloat162_rn(a, b);
    return *reinterpret_cast<uint32_t*>(&t);
}

__device__ __forceinline__ void split2(float a, float b, uint32_t& hi, uint32_t& lo) {
    float h0 = __bfloat162float(__float2bfloat16_rn(a));
    float h1 = __bfloat162float(__float2bfloat16_rn(b));
    hi = pack_bf16x2(h0, h1);
    lo = pack_bf16x2(a - h0, b - h1);
}

#define LDMX4(r, addr) \
    asm volatile("ldmatrix.sync.aligned.m8n8.x4.shared.b16 {%0,%1,%2,%3}, [%4];" \
        : "=r"((r)[0]), "=r"((r)[1]), "=r"((r)[2]), "=r"((r)[3]) : "r"(addr))

#define LDMX4T(r, addr) \
    asm volatile("ldmatrix.sync.aligned.m8n8.x4.trans.shared.b16 {%0,%1,%2,%3}, [%4];" \
        : "=r"((r)[0]), "=r"((r)[1]), "=r"((r)[2]), "=r"((r)[3]) : "r"(addr))

#define MMA_BF16(d, a, b0, b1) \
    asm volatile("mma.sync.aligned.m16n8k16.row.col.f32.bf16.bf16.f32 " \
        "{%0,%1,%2,%3}, {%4,%5,%6,%7}, {%8,%9}, {%0,%1,%2,%3};" \
        : "+f"((d)[0]), "+f"((d)[1]), "+f"((d)[2]), "+f"((d)[3]) \
        : "r"((a)[0]), "r"((a)[1]), "r"((a)[2]), "r"((a)[3]), "r"(b0), "r"(b1))

// GEMM smem tile: logical [128 rows][32 k], two rows per 128B physical row.
__device__ __forceinline__ uint32_t sw_off(int r, int bytecol) {
    int prow  = r >> 1;
    int chunk = ((r & 1) << 2) | (bytecol >> 4);
    return (uint32_t)(prow * 128 + ((chunk ^ (prow & 7)) << 4) + (bytecol & 15));
}

// Attention smem tile: [rows][64 bf16] = 128B/row, canonical SW128.
__device__ __forceinline__ uint32_t sw128o(int r, int bc) {
    return (uint32_t)(r * 128 + ((((bc >> 4) ^ (r & 7)) << 4)) + (bc & 15));
}

// ===========================================================================
// Tensor-core GEMM via mma.sync (bf16x3 fp32 emulation)  [unchanged from R3]
// ===========================================================================
#define GBK        32
#define GTILE      8192
#define GBUF       (4 * GTILE)
#define GSMEM_TOT  (2 * GBUF)

__global__ __launch_bounds__(256, 1)
void gemm_mma(const float* __restrict__ A, const float* __restrict__ W,
              const float* __restrict__ bias, float* __restrict__ out, int mode)
{
    extern __shared__ char smem[];
    const uint32_t sb = smem_u32(smem);
    const int tid  = threadIdx.x;
    const int wid  = tid >> 5;
    const int lane = tid & 31;
    const int wm = wid & 3;
    const int wn = wid >> 2;
    const int n0 = blockIdx.y << 7;
    const int m0 = blockIdx.x << 7;

    float acc[2][8][4];
#pragma unroll
    for (int mt = 0; mt < 2; mt++)
#pragma unroll
        for (int nt = 0; nt < 8; nt++)
#pragma unroll
            for (int j = 0; j < 4; j++) acc[mt][nt][j] = 0.f;

    float4 ar[4], wr[4];

    auto G2R = [&](int c) {
        const int k0 = c << 5;
#pragma unroll
        for (int i = 0; i < 4; i++) {
            const int idx = (i << 8) + tid;
            const int row = idx >> 3;
            const int cg  = (idx & 7) << 2;
            ar[i] = *(const float4*)&A[(size_t)(n0 + row) * DIM + k0 + cg];
            wr[i] = *(const float4*)&W[(size_t)(m0 + row) * DIM + k0 + cg];
        }
    };

    auto R2S = [&](int b) {
        char* buf = smem + b * GBUF;
#pragma unroll
        for (int i = 0; i < 4; i++) {
            const int idx = (i << 8) + tid;
            const int row = idx >> 3;
            const int bytecol = (idx & 7) << 3;
            const uint32_t so = sw_off(row, bytecol);
            float4 av = ar[i], wv = wr[i];
            uint2 ahp, alp, whp, wlp;
            split2(av.x, av.y, ahp.x, alp.x);
            split2(av.z, av.w, ahp.y, alp.y);
            split2(wv.x, wv.y, whp.x, wlp.x);
            split2(wv.z, wv.w, whp.y, wlp.y);
            *(uint2*)(buf + 0 * GTILE + so) = ahp;
            *(uint2*)(buf + 1 * GTILE + so) = alp;
            *(uint2*)(buf + 2 * GTILE + so) = whp;
            *(uint2*)(buf + 3 * GTILE + so) = wlp;
        }
    };

    auto compute = [&](int b) {
        const uint32_t buf = sb + b * GBUF;
#pragma unroll
        for (int ks = 0; ks < 2; ks++) {
            uint32_t a_h[2][4], a_l[2][4], b_h[4][4], b_l[4][4];
#pragma unroll
            for (int mt = 0; mt < 2; mt++) {
                const int r  = wm * 32 + mt * 16 + (lane & 15);
                const int bc = ks * 32 + ((lane >> 4) & 1) * 16;
                const uint32_t o = sw_off(r, bc);
                LDMX4(a_h[mt], buf + 0 * GTILE + o);
                LDMX4(a_l[mt], buf + 1 * GTILE + o);
            }
#pragma unroll
            for (int bt = 0; bt < 4; bt++) {
                const int rn = wn * 64 + bt * 16 + ((lane >> 4) << 3) + (lane & 7);
                const int bc = ks * 32 + ((lane >> 3) & 1) * 16;
                const uint32_t o = sw_off(rn, bc);
                LDMX4(b_h[bt], buf + 2 * GTILE + o);
                LDMX4(b_l[bt], buf + 3 * GTILE + o);
            }
#pragma unroll
            for (int mt = 0; mt < 2; mt++)
#pragma unroll
                for (int nt = 0; nt < 8; nt++)
                    MMA_BF16(acc[mt][nt], a_h[mt],
                             b_h[nt >> 1][(nt & 1) << 1], b_h[nt >> 1][((nt & 1) << 1) + 1]);
#pragma unroll
            for (int mt = 0; mt < 2; mt++)
#pragma unroll
                for (int nt = 0; nt < 8; nt++)
                    MMA_BF16(acc[mt][nt], a_h[mt],
                             b_l[nt >> 1][(nt & 1) << 1], b_l[nt >> 1][((nt & 1) << 1) + 1]);
#pragma unroll
            for (int mt = 0; mt < 2; mt++)
#pragma unroll
                for (int nt = 0; nt < 8; nt++)
                    MMA_BF16(acc[mt][nt], a_l[mt],
                             b_h[nt >> 1][(nt & 1) << 1], b_h[nt >> 1][((nt & 1) << 1) + 1]);
        }
    };

    G2R(0); R2S(0); __syncthreads();
    for (int c = 0; c < DIM / GBK; c++) {
        if (c < DIM / GBK - 1) G2R(c + 1);
        compute(c & 1);
        if (c < DIM / GBK - 1) { R2S((c + 1) & 1); __syncthreads(); }
    }

#pragma unroll
    for (int mt = 0; mt < 2; mt++) {
        const int r0 = n0 + wm * 32 + mt * 16 + (lane >> 2);
#pragma unroll
        for (int nt = 0; nt < 8; nt++) {
            const int m = m0 + wn * 64 + nt * 8 + ((lane & 3) << 1);
            const float2 bv = *(const float2*)&bias[m];
            float2 v0 = make_float2(acc[mt][nt][0] + bv.x, acc[mt][nt][1] + bv.y);
            float2 v1 = make_float2(acc[mt][nt][2] + bv.x, acc[mt][nt][3] + bv.y);
            if (mode == 0) {
                const int h = m >> 6, dk = m & 63;
                {
                    const int n = r0, bi = n >> 11, s = n & 2047;
                    *(float2*)&out[(((size_t)bi * NH + h) * SEQ + s) * HD + dk] = v0;
                }
                {
                    const int n = r0 + 8, bi = n >> 11, s = n & 2047;
                    *(float2*)&out[(((size_t)bi * NH + h) * SEQ + s) * HD + dk] = v1;
                }
            } else {
                *(float2*)&out[(size_t)r0 * DIM + m] = v0;
                *(float2*)&out[(size_t)(r0 + 8) * DIM + m] = v1;
            }
        }
    }
}

// ===========================================================================
// Tensor-core causal flash attention (bf16x3 for QK and PV, fp32 softmax).
// CTA: 128 q-rows x 64-key tiles. 8 warps, each owns 16 q-rows.
// Q/K/V: [B*H, S, HD]. Output C: [B, S, D] head-interleaved.
// ===========================================================================
#define ASMEM_QH 0
#define ASMEM_QL 16384
#define ASMEM_KH 32768
#define ASMEM_KL 40960
#define ASMEM_VH 49152
#define ASMEM_VL 57344
#define ASMEM_TOT 65536

__global__ __launch_bounds__(256, 1)
void flash_mma(const float* __restrict__ Q, const float* __restrict__ K,
               const float* __restrict__ V, float* __restrict__ C)
{
    extern __shared__ char smem[];
    const uint32_t sb = smem_u32(smem);
    const int tid  = threadIdx.x;
    const int w    = tid >> 5;
    const int lane = tid & 31;
    const int qt = blockIdx.x;
    const int bh = blockIdx.y;
    const int q0 = qt << 7;

    const float* Qb = Q + (size_t)bh * SEQ * HD;
    const float* Kb = K + (size_t)bh * SEQ * HD;
    const float* Vb = V + (size_t)bh * SEQ * HD;

    // Load Q tile [128][64] fp32 -> bf16 hi/lo in smem
#pragma unroll
    for (int i = 0; i < 8; i++) {
        const int idx = (i << 8) + tid;        // 0..2047
        const int row = idx >> 4;              // 0..127
        const int c4  = (idx & 15) << 2;       // 0,4,...,60
        float4 qv = *(const float4*)&Qb[(size_t)(q0 + row) * HD + c4];
        uint2 hi, lo;
        split2(qv.x, qv.y, hi.x, lo.x);
        split2(qv.z, qv.w, hi.y, lo.y);
        const uint32_t so = sw128o(row, c4 * 2);
        *(uint2*)(smem + ASMEM_QH + so) = hi;
        *(uint2*)(smem + ASMEM_QL + so) = lo;
    }

    float o[8][4];
    float mx[2], li[2];
#pragma unroll
    for (int nt = 0; nt < 8; nt++)
#pragma unroll
        for (int j = 0; j < 4; j++) o[nt][j] = 0.f;
    mx[0] = mx[1] = -INFINITY;
    li[0] = li[1] = 0.f;

    const int jt_end = 2 * qt + 2;
    const int wrow_max = q0 + w * 16 + 15;     // warp's max q row

    for (int jt = 0; jt < jt_end; jt++) {
        const int k0 = jt << 6;
        __syncthreads();   // prior iteration's K/V reads complete

        // Load K/V tile [64][64] fp32 -> bf16 hi/lo
#pragma unroll
        for (int i = 0; i < 4; i++) {
            const int idx = (i << 8) + tid;    // 0..1023
            const int row = idx >> 4;          // 0..63
            const int c4  = (idx & 15) << 2;
            const uint32_t so = sw128o(row, c4 * 2);
            float4 kv = *(const float4*)&Kb[(size_t)(k0 + row) * HD + c4];
            uint2 hi, lo;
            split2(kv.x, kv.y, hi.x, lo.x);
            split2(kv.z, kv.w, hi.y, lo.y);
            *(uint2*)(smem + ASMEM_KH + so) = hi;
            *(uint2*)(smem + ASMEM_KL + so) = lo;
            float4 vv = *(const float4*)&Vb[(size_t)(k0 + row) * HD + c4];
            split2(vv.x, vv.y, hi.x, lo.x);
            split2(vv.z, vv.w, hi.y, lo.y);
            *(uint2*)(smem + ASMEM_VH + so) = hi;
            *(uint2*)(smem + ASMEM_VL + so) = lo;
        }
        __syncthreads();

        if (k0 <= wrow_max) {   // warp-uniform: skip fully-masked tiles
            // ---- S = Q K^T (bf16x3) ----
            float s[8][4];
#pragma unroll
            for (int nt = 0; nt < 8; nt++)
#pragma unroll
                for (int j = 0; j < 4; j++) s[nt][j] = 0.f;

#pragma unroll
            for (int ks = 0; ks < 4; ks++) {
                uint32_t qh[4], ql[4];
                const uint32_t qo = sw128o(w * 16 + (lane & 15),
                                           ks * 32 + ((lane >> 4) & 1) * 16);
                LDMX4(qh, sb + ASMEM_QH + qo);
                LDMX4(ql, sb + ASMEM_QL + qo);
#pragma unroll
                for (int bt = 0; bt < 4; bt++) {
                    const int rn = bt * 16 + ((lane >> 4) << 3) + (lane & 7);
                    const int bc = ks * 32 + ((lane >> 3) & 1) * 16;
                    const uint32_t ko = sw128o(rn, bc);
                    uint32_t kh[4], kl[4];
                    LDMX4(kh, sb + ASMEM_KH + ko);
                    LDMX4(kl, sb + ASMEM_KL + ko);
                    MMA_BF16(s[2 * bt],     qh, kh[0], kh[1]);
                    MMA_BF16(s[2 * bt + 1], qh, kh[2], kh[3]);
                    MMA_BF16(s[2 * bt],     qh, kl[0], kl[1]);
                    MMA_BF16(s[2 * bt + 1], qh, kl[2], kl[3]);
                    MMA_BF16(s[2 * bt],     ql, kh[0], kh[1]);
                    MMA_BF16(s[2 * bt + 1], ql, kh[2], kh[3]);
                }
            }

            // ---- scale + causal mask ----
            const int r0g = q0 + w * 16 + (lane >> 2);
            const bool diag = (jt >= 2 * qt);
#pragma unroll
            for (int nt = 0; nt < 8; nt++)
#pragma unroll
                for (int j = 0; j < 4; j++) {
                    float v = s[nt][j] * QK_SCALE;
                    if (diag) {
                        const int col = k0 + nt * 8 + ((lane & 3) << 1) + (j & 1);
                        const int row = r0g + ((j >> 1) << 3);
                        if (col > row) v = -INFINITY;
                    }
                    s[nt][j] = v;
                }

            // ---- online softmax (two row-halves per thread) ----
#pragma unroll
            for (int hf = 0; hf < 2; hf++) {
                float rm = -INFINITY;
#pragma unroll
                for (int nt = 0; nt < 8; nt++)
                    rm = fmaxf(rm, fmaxf(s[nt][2 * hf], s[nt][2 * hf + 1]));
                rm = fmaxf(rm, __shfl_xor_sync(0xffffffffu, rm, 1));
                rm = fmaxf(rm, __shfl_xor_sync(0xffffffffu, rm, 2));
                const float mn = fmaxf(mx[hf], rm);
                const float al = __expf(mx[hf] - mn);
                mx[hf] = mn;
                float rs = 0.f;
#pragma unroll
                for (int nt = 0; nt < 8; nt++) {
                    float e0 = __expf(s[nt][2 * hf] - mn);
                    float e1 = __expf(s[nt][2 * hf + 1] - mn);
                    s[nt][2 * hf] = e0; s[nt][2 * hf + 1] = e1;
                    rs += e0 + e1;
                }
                rs += __shfl_xor_sync(0xffffffffu, rs, 1);
                rs += __shfl_xor_sync(0xffffffffu, rs, 2);
                li[hf] = li[hf] * al + rs;
#pragma unroll
                for (int nt = 0; nt < 8; nt++) {
                    o[nt][2 * hf]     *= al;
                    o[nt][2 * hf + 1] *= al;
                }
            }

            // ---- O += P V (bf16x3), P from S accumulators ----
#pragma unroll
            for (int kk = 0; kk < 4; kk++) {
                uint32_t ph[4], pl[4];
                split2(s[2 * kk][0],     s[2 * kk][1],     ph[0], pl[0]);
                split2(s[2 * kk][2],     s[2 * kk][3],     ph[1], pl[1]);
                split2(s[2 * kk + 1][0], s[2 * kk + 1][1], ph[2], pl[2]);
                split2(s[2 * kk + 1][2], s[2 * kk + 1][3], ph[3], pl[3]);
#pragma unroll
                for (int pr = 0; pr < 4; pr++) {
                    const int vrow = kk * 16 + (lane & 7) + (((lane >> 3) & 1) << 3);
                    const int vbc  = pr * 32 + ((lane >> 4) << 4);
                    const uint32_t vo = sw128o(vrow, vbc);
                    uint32_t vh[4], vl[4];
                    LDMX4T(vh, sb + ASMEM_VH + vo);
                    LDMX4T(vl, sb + ASMEM_VL + vo);
                    MMA_BF16(o[2 * pr],     ph, vh[0], vh[1]);
                    MMA_BF16(o[2 * pr + 1], ph, vh[2], vh[3]);
                    MMA_BF16(o[2 * pr],     pl, vh[0], vh[1]);
                    MMA_BF16(o[2 * pr + 1], pl, vh[2], vh[3]);
                    MMA_BF16(o[2 * pr],     ph, vl[0], vl[1]);
                    MMA_BF16(o[2 * pr + 1], ph, vl[2], vl[3]);
                }
            }
        }
    }

    // ---- epilogue: C[b, s, h*HD + dk] = o / l ----
    const int bi = bh >> 4;
    const int h  = bh & 15;
#pragma unroll
    for (int hf = 0; hf < 2; hf++) {
        const float inv = 1.f / li[hf];
        const int srow = q0 + w * 16 + (lane >> 2) + hf * 8;
#pragma unroll
        for (int nt = 0; nt < 8; nt++) {
            const int col = h * HD + nt * 8 + ((lane & 3) << 1);
            float2 r = make_float2(o[nt][2 * hf] * inv, o[nt][2 * hf + 1] * inv);
            *(float2*)&C[((size_t)bi * SEQ + srow) * DIM + col] = r;
        }
    }
}

// ---------------------------------------------------------------------------
// Launch
// ---------------------------------------------------------------------------
extern "C" void kernel_launch(void* const* d_in, const int* in_sizes, int n_in,
                              void* d_out, int out_size)
{
    (void)in_sizes; (void)n_in; (void)out_size;
    const float* x  = (const float*)d_in[0];
    const float* Wq = (const float*)d_in[2];
    const float* bq = (const float*)d_in[3];
    const float* Wk = (const float*)d_in[4];
    const float* bk = (const float*)d_in[5];
    const float* Wv = (const float*)d_in[6];
    const float* bv = (const float*)d_in[7];
    const float* Wo = (const float*)d_in[8];
    const float* bo = (const float*)d_in[9];
    float* out = (float*)d_out;

    float *Qp, *Kp, *Vp, *Cp;
    cudaGetSymbolAddress((void**)&Qp, g_Q);
    cudaGetSymbolAddress((void**)&Kp, g_K);
    cudaGetSymbolAddress((void**)&Vp, g_V);
    cudaGetSymbolAddress((void**)&Cp, g_C);

    cudaFuncSetAttribute(gemm_mma, cudaFuncAttributeMaxDynamicSharedMemorySize,
                         GSMEM_TOT);
    cudaFuncSetAttribute(flash_mma, cudaFuncAttributeMaxDynamicSharedMemorySize,
                         ASMEM_TOT);

    dim3 gemm_grid(DIM / 128, NR / 128);   // 8 x 64
    gemm_mma<<<gemm_grid, 256, GSMEM_TOT>>>(x, Wq, bq, Qp, 0);
    gemm_mma<<<gemm_grid, 256, GSMEM_TOT>>>(x, Wk, bk, Kp, 0);
    gemm_mma<<<gemm_grid, 256, GSMEM_TOT>>>(x, Wv, bv, Vp, 0);

    dim3 attn_grid(SEQ / 128, BATCH * NH);  // 16 x 64
    flash_mma<<<attn_grid, 256, ASMEM_TOT>>>(Qp, Kp, Vp, Cp);

    gemm_mma<<<gemm_grid, 256, GSMEM_TOT>>>(Cp, Wo, bo, out, 1);
}

// round 5
// speedup vs baseline: 2.8982x; 1.0683x over previous
#include <cuda_runtime.h>
#include <cuda_bf16.h>
#include <math.h>
#include <stdint.h>

// Problem constants
#define BATCH 4
#define SEQ   2048
#define DIM   1024
#define NH    16
#define HD    64
#define NR    (BATCH * SEQ)        // 8192 rows
#define QK_SCALE 0.125f            // 1/sqrt(64)

typedef __nv_bfloat16 bf16;

// Persistent scratch (allocation-free: __device__ globals)
__device__ bf16 g_Xh[(size_t)NR * DIM];
__device__ bf16 g_Xl[(size_t)NR * DIM];
__device__ bf16 g_Wh[4][(size_t)DIM * DIM];
__device__ bf16 g_Wl[4][(size_t)DIM * DIM];
__device__ bf16 g_Qh[(size_t)NR * DIM];
__device__ bf16 g_Ql[(size_t)NR * DIM];
__device__ bf16 g_Kh[(size_t)NR * DIM];
__device__ bf16 g_Kl[(size_t)NR * DIM];
__device__ bf16 g_Vh[(size_t)NR * DIM];
__device__ bf16 g_Vl[(size_t)NR * DIM];
__device__ bf16 g_Ch[(size_t)NR * DIM];
__device__ bf16 g_Cl[(size_t)NR * DIM];

// ===========================================================================
// Helpers
// ===========================================================================
__device__ __forceinline__ uint32_t smem_u32(const void* p) {
    uint32_t a;
    asm("{ .reg .u64 t; cvta.to.shared.u64 t, %1; cvt.u32.u64 %0, t; }"
        : "=r"(a) : "l"(p));
    return a;
}

__device__ __forceinline__ uint32_t pack_bf16x2(float a, float b) {
    __nv_bfloat162 t = __floats2bfloat162_rn(a, b);
    return *reinterpret_cast<uint32_t*>(&t);
}

__device__ __forceinline__ void split2(float a, float b, uint32_t& hi, uint32_t& lo) {
    float h0 = __bfloat162float(__float2bfloat16_rn(a));
    float h1 = __bfloat162float(__float2bfloat16_rn(b));
    hi = pack_bf16x2(h0, h1);
    lo = pack_bf16x2(a - h0, b - h1);
}

#define LDMX4(r, addr) \
    asm volatile("ldmatrix.sync.aligned.m8n8.x4.shared.b16 {%0,%1,%2,%3}, [%4];" \
        : "=r"((r)[0]), "=r"((r)[1]), "=r"((r)[2]), "=r"((r)[3]) : "r"(addr))

#define LDMX4T(r, addr) \
    asm volatile("ldmatrix.sync.aligned.m8n8.x4.trans.shared.b16 {%0,%1,%2,%3}, [%4];" \
        : "=r"((r)[0]), "=r"((r)[1]), "=r"((r)[2]), "=r"((r)[3]) : "r"(addr))

#define MMA_BF16(d, a, b0, b1) \
    asm volatile("mma.sync.aligned.m16n8k16.row.col.f32.bf16.bf16.f32 " \
        "{%0,%1,%2,%3}, {%4,%5,%6,%7}, {%8,%9}, {%0,%1,%2,%3};" \
        : "+f"((d)[0]), "+f"((d)[1]), "+f"((d)[2]), "+f"((d)[3]) \
        : "r"((a)[0]), "r"((a)[1]), "r"((a)[2]), "r"((a)[3]), "r"(b0), "r"(b1))

#define CP_ASYNC16(dst, src) \
    asm volatile("cp.async.cg.shared.global [%0], [%1], 16;" :: "r"(dst), "l"(src))
#define CP_COMMIT() asm volatile("cp.async.commit_group;")
#define CP_WAIT(n)  asm volatile("cp.async.wait_group %0;" :: "n"(n))

// GEMM smem tile: logical [128 rows][32 k bf16], two rows per 128B phys row.
__device__ __forceinline__ uint32_t sw_off(int r, int bytecol) {
    int prow  = r >> 1;
    int chunk = ((r & 1) << 2) | (bytecol >> 4);
    return (uint32_t)(prow * 128 + ((chunk ^ (prow & 7)) << 4) + (bytecol & 15));
}

// Attention smem tile: [rows][64 bf16] = 128B/row, canonical SW128.
__device__ __forceinline__ uint32_t sw128o(int r, int bc) {
    return (uint32_t)(r * 128 + ((((bc >> 4) ^ (r & 7)) << 4)) + (bc & 15));
}

// ===========================================================================
// Pre-split: fp32 -> bf16 hi/lo (elementwise, vectorized)
// ===========================================================================
__global__ void split_f32(const float* __restrict__ in, bf16* __restrict__ hi,
                          bf16* __restrict__ lo, int n4)
{
    int i = blockIdx.x * blockDim.x + threadIdx.x;
    if (i < n4) {
        float4 v = ((const float4*)in)[i];
        uint2 h, l;
        split2(v.x, v.y, h.x, l.x);
        split2(v.z, v.w, h.y, l.y);
        ((uint2*)hi)[i] = h;
        ((uint2*)lo)[i] = l;
    }
}

// ===========================================================================
// Tensor-core GEMM, bf16 hi/lo inputs, cp.async 3-stage pipeline.
// out[n,m] = sum_k A[n,k]*W[m,k] + bias[m]  (A = Ah+Al, W = Wh+Wl, bf16x3)
// Tile 128x128, BK=32, 256 threads, warps 4(M) x 2(N).
// mode 0: split-scatter into [B,H,S,DK] bf16 hi/lo (outH/outL)
// mode 1: fp32 row-major [NR][DIM] (outF)
// ===========================================================================
#define GSTG   32768                 // AH,AL,WH,WL tiles of 8KB
#define GSMEM_TOT (3 * GSTG)         // 98304

__global__ __launch_bounds__(256, 1)
void gemm_mma(const bf16* __restrict__ Ah, const bf16* __restrict__ Al,
              const bf16* __restrict__ Wh, const bf16* __restrict__ Wl,
              const float* __restrict__ bias, float* __restrict__ outF,
              bf16* __restrict__ outH, bf16* __restrict__ outL, int mode)
{
    extern __shared__ char smem[];
    const uint32_t sb = smem_u32(smem);
    const int tid  = threadIdx.x;
    const int wid  = tid >> 5;
    const int lane = tid & 31;
    const int wm = wid & 3;
    const int wn = wid >> 2;
    const int n0 = blockIdx.y << 7;
    const int m0 = blockIdx.x << 7;

    float acc[2][8][4];
#pragma unroll
    for (int mt = 0; mt < 2; mt++)
#pragma unroll
        for (int nt = 0; nt < 8; nt++)
#pragma unroll
            for (int j = 0; j < 4; j++) acc[mt][nt][j] = 0.f;

    auto issue = [&](int c, int stg) {
        const int k0 = c << 5;
        const uint32_t base = sb + stg * GSTG;
#pragma unroll
        for (int i = 0; i < 8; i++) {
            const int idx = (i << 8) + tid;     // 0..2047
            const int arr = idx >> 9;           // 0..3 (per-i compile-time-ish)
            const int rem = idx & 511;
            const int row = rem >> 2;           // 0..127
            const int ch  = rem & 3;            // 16B chunk
            const uint32_t dst = base + arr * 8192 + sw_off(row, ch << 4);
            const bf16* g;
            if (arr == 0)      g = Ah + (size_t)(n0 + row) * DIM + k0 + (ch << 3);
            else if (arr == 1) g = Al + (size_t)(n0 + row) * DIM + k0 + (ch << 3);
            else if (arr == 2) g = Wh + (size_t)(m0 + row) * DIM + k0 + (ch << 3);
            else               g = Wl + (size_t)(m0 + row) * DIM + k0 + (ch << 3);
            CP_ASYNC16(dst, g);
        }
        CP_COMMIT();
    };

    auto compute = [&](int stg) {
        const uint32_t buf = sb + stg * GSTG;
#pragma unroll
        for (int ks = 0; ks < 2; ks++) {
            uint32_t a_h[2][4], a_l[2][4], b_h[4][4], b_l[4][4];
#pragma unroll
            for (int mt = 0; mt < 2; mt++) {
                const int r  = wm * 32 + mt * 16 + (lane & 15);
                const int bc = ks * 32 + ((lane >> 4) & 1) * 16;
                const uint32_t o = sw_off(r, bc);
                LDMX4(a_h[mt], buf + 0 * 8192 + o);
                LDMX4(a_l[mt], buf + 1 * 8192 + o);
            }
#pragma unroll
            for (int bt = 0; bt < 4; bt++) {
                const int rn = wn * 64 + bt * 16 + ((lane >> 4) << 3) + (lane & 7);
                const int bc = ks * 32 + ((lane >> 3) & 1) * 16;
                const uint32_t o = sw_off(rn, bc);
                LDMX4(b_h[bt], buf + 2 * 8192 + o);
                LDMX4(b_l[bt], buf + 3 * 8192 + o);
            }
#pragma unroll
            for (int mt = 0; mt < 2; mt++)
#pragma unroll
                for (int nt = 0; nt < 8; nt++)
                    MMA_BF16(acc[mt][nt], a_h[mt],
                             b_h[nt >> 1][(nt & 1) << 1], b_h[nt >> 1][((nt & 1) << 1) + 1]);
#pragma unroll
            for (int mt = 0; mt < 2; mt++)
#pragma unroll
                for (int nt = 0; nt < 8; nt++)
                    MMA_BF16(acc[mt][nt], a_h[mt],
                             b_l[nt >> 1][(nt & 1) << 1], b_l[nt >> 1][((nt & 1) << 1) + 1]);
#pragma unroll
            for (int mt = 0; mt < 2; mt++)
#pragma unroll
                for (int nt = 0; nt < 8; nt++)
                    MMA_BF16(acc[mt][nt], a_l[mt],
                             b_h[nt >> 1][(nt & 1) << 1], b_h[nt >> 1][((nt & 1) << 1) + 1]);
        }
    };

    issue(0, 0);
    issue(1, 1);
    for (int c = 0; c < DIM / 32; c++) {
        if (c + 2 < DIM / 32) issue(c + 2, (c + 2) % 3);
        if (c + 2 < DIM / 32)      { CP_WAIT(2); }
        else if (c + 1 < DIM / 32) { CP_WAIT(1); }
        else                       { CP_WAIT(0); }
        __syncthreads();
        compute(c % 3);
        __syncthreads();
    }

    // Epilogue
#pragma unroll
    for (int mt = 0; mt < 2; mt++) {
        const int r0 = n0 + wm * 32 + mt * 16 + (lane >> 2);
#pragma unroll
        for (int nt = 0; nt < 8; nt++) {
            const int m = m0 + wn * 64 + nt * 8 + ((lane & 3) << 1);
            const float2 bv = *(const float2*)&bias[m];
            float2 v0 = make_float2(acc[mt][nt][0] + bv.x, acc[mt][nt][1] + bv.y);
            float2 v1 = make_float2(acc[mt][nt][2] + bv.x, acc[mt][nt][3] + bv.y);
            if (mode == 0) {
                const int h = m >> 6, dk = m & 63;
                uint32_t hi, lo;
                {
                    const int n = r0, bi = n >> 11, s = n & 2047;
                    const size_t off = (((size_t)bi * NH + h) * SEQ + s) * HD + dk;
                    split2(v0.x, v0.y, hi, lo);
                    *(uint32_t*)&outH[off] = hi;
                    *(uint32_t*)&outL[off] = lo;
                }
                {
                    const int n = r0 + 8, bi = n >> 11, s = n & 2047;
                    const size_t off = (((size_t)bi * NH + h) * SEQ + s) * HD + dk;
                    split2(v1.x, v1.y, hi, lo);
                    *(uint32_t*)&outH[off] = hi;
                    *(uint32_t*)&outL[off] = lo;
                }
            } else {
                *(float2*)&outF[(size_t)r0 * DIM + m] = v0;
                *(float2*)&outF[(size_t)(r0 + 8) * DIM + m] = v1;
            }
        }
    }
}

// ===========================================================================
// Tensor-core causal flash attention, bf16 hi/lo inputs via cp.async.
// CTA: 128 q-rows x 64-key tiles. 8 warps, each owns 16 q-rows.
// Writes context as bf16 hi/lo [B, S, D] head-interleaved.
// ===========================================================================
#define AQ_H  0
#define AQ_L  16384
#define AKV0  32768
#define AKVSTG 32768                  // KH,KL,VH,VL tiles of 8KB
#define ASMEM_TOT (AKV0 + 2 * AKVSTG) // 98304

__global__ __launch_bounds__(256, 1)
void flash_mma(const bf16* __restrict__ Qh, const bf16* __restrict__ Ql,
               const bf16* __restrict__ Kh, const bf16* __restrict__ Kl,
               const bf16* __restrict__ Vh, const bf16* __restrict__ Vl,
               bf16* __restrict__ Ch, bf16* __restrict__ Cl)
{
    extern __shared__ char smem[];
    const uint32_t sb = smem_u32(smem);
    const int tid  = threadIdx.x;
    const int w    = tid >> 5;
    const int lane = tid & 31;
    const int qt = blockIdx.x;
    const int bh = blockIdx.y;
    const int q0 = qt << 7;

    const size_t bhoff = (size_t)bh * SEQ * HD;

    auto issueQ = [&]() {
#pragma unroll
        for (int i = 0; i < 8; i++) {
            const int idx = (i << 8) + tid;    // 0..2047
            const int arr = idx >> 10;         // 0=H, 1=L
            const int rem = idx & 1023;
            const int row = rem >> 3;          // 0..127
            const int ch  = rem & 7;
            const uint32_t dst = sb + (arr ? AQ_L : AQ_H) + sw128o(row, ch << 4);
            const bf16* g = (arr ? Ql : Qh) + bhoff + (size_t)(q0 + row) * HD + (ch << 3);
            CP_ASYNC16(dst, g);
        }
    };

    auto issueKV = [&](int jt, int b) {
        const int k0 = jt << 6;
        const uint32_t base = sb + AKV0 + b * AKVSTG;
#pragma unroll
        for (int i = 0; i < 8; i++) {
            const int idx = (i << 8) + tid;    // 0..2047
            const int arr = idx >> 9;          // 0:KH 1:KL 2:VH 3:VL
            const int rem = idx & 511;
            const int row = rem >> 3;          // 0..63
            const int ch  = rem & 7;
            const uint32_t dst = base + arr * 8192 + sw128o(row, ch << 4);
            const bf16* g;
            if (arr == 0)      g = Kh + bhoff + (size_t)(k0 + row) * HD + (ch << 3);
            else if (arr == 1) g = Kl + bhoff + (size_t)(k0 + row) * HD + (ch << 3);
            else if (arr == 2) g = Vh + bhoff + (size_t)(k0 + row) * HD + (ch << 3);
            else               g = Vl + bhoff + (size_t)(k0 + row) * HD + (ch << 3);
            CP_ASYNC16(dst, g);
        }
        CP_COMMIT();
    };

    float o[8][4];
    float mx[2], li[2];
#pragma unroll
    for (int nt = 0; nt < 8; nt++)
#pragma unroll
        for (int j = 0; j < 4; j++) o[nt][j] = 0.f;
    mx[0] = mx[1] = -INFINITY;
    li[0] = li[1] = 0.f;

    const int jt_end = 2 * qt + 2;
    const int wrow_max = q0 + w * 16 + 15;

    issueQ();
    issueKV(0, 0);      // Q + KV0 in group 0

    for (int jt = 0; jt < jt_end; jt++) {
        const int k0 = jt << 6;
        if (jt + 1 < jt_end) {
            issueKV(jt + 1, (jt + 1) & 1);
            CP_WAIT(1);
        } else {
            CP_WAIT(0);
        }
        __syncthreads();

        if (k0 <= wrow_max) {
            const uint32_t kvb = sb + AKV0 + (jt & 1) * AKVSTG;

            // ---- S = Q K^T (bf16x3) ----
            float s[8][4];
#pragma unroll
            for (int nt = 0; nt < 8; nt++)
#pragma unroll
                for (int j = 0; j < 4; j++) s[nt][j] = 0.f;

#pragma unroll
            for (int ks = 0; ks < 4; ks++) {
                uint32_t qh[4], ql[4];
                const uint32_t qo = sw128o(w * 16 + (lane & 15),
                                           ks * 32 + ((lane >> 4) & 1) * 16);
                LDMX4(qh, sb + AQ_H + qo);
                LDMX4(ql, sb + AQ_L + qo);
#pragma unroll
                for (int bt = 0; bt < 4; bt++) {
                    const int rn = bt * 16 + ((lane >> 4) << 3) + (lane & 7);
                    const int bc = ks * 32 + ((lane >> 3) & 1) * 16;
                    const uint32_t ko = sw128o(rn, bc);
                    uint32_t kh[4], kl[4];
                    LDMX4(kh, kvb + 0 * 8192 + ko);
                    LDMX4(kl, kvb + 1 * 8192 + ko);
                    MMA_BF16(s[2 * bt],     qh, kh[0], kh[1]);
                    MMA_BF16(s[2 * bt + 1], qh, kh[2], kh[3]);
                    MMA_BF16(s[2 * bt],     qh, kl[0], kl[1]);
                    MMA_BF16(s[2 * bt + 1], qh, kl[2], kl[3]);
                    MMA_BF16(s[2 * bt],     ql, kh[0], kh[1]);
                    MMA_BF16(s[2 * bt + 1], ql, kh[2], kh[3]);
                }
            }

            // ---- scale + causal mask ----
            const int r0g = q0 + w * 16 + (lane >> 2);
            const bool diag = (jt >= 2 * qt);
#pragma unroll
            for (int nt = 0; nt < 8; nt++)
#pragma unroll
                for (int j = 0; j < 4; j++) {
                    float v = s[nt][j] * QK_SCALE;
                    if (diag) {
                        const int col = k0 + nt * 8 + ((lane & 3) << 1) + (j & 1);
                        const int row = r0g + ((j >> 1) << 3);
                        if (col > row) v = -INFINITY;
                    }
                    s[nt][j] = v;
                }

            // ---- online softmax ----
#pragma unroll
            for (int hf = 0; hf < 2; hf++) {
                float rm = -INFINITY;
#pragma unroll
                for (int nt = 0; nt < 8; nt++)
                    rm = fmaxf(rm, fmaxf(s[nt][2 * hf], s[nt][2 * hf + 1]));
                rm = fmaxf(rm, __shfl_xor_sync(0xffffffffu, rm, 1));
                rm = fmaxf(rm, __shfl_xor_sync(0xffffffffu, rm, 2));
                const float mn = fmaxf(mx[hf], rm);
                const float al = __expf(mx[hf] - mn);
                mx[hf] = mn;
                float rs = 0.f;
#pragma unroll
                for (int nt = 0; nt < 8; nt++) {
                    float e0 = __expf(s[nt][2 * hf] - mn);
                    float e1 = __expf(s[nt][2 * hf + 1] - mn);
                    s[nt][2 * hf] = e0; s[nt][2 * hf + 1] = e1;
                    rs += e0 + e1;
                }
                rs += __shfl_xor_sync(0xffffffffu, rs, 1);
                rs += __shfl_xor_sync(0xffffffffu, rs, 2);
                li[hf] = li[hf] * al + rs;
#pragma unroll
                for (int nt = 0; nt < 8; nt++) {
                    o[nt][2 * hf]     *= al;
                    o[nt][2 * hf + 1] *= al;
                }
            }

            // ---- O += P V (bf16x3) ----
#pragma unroll
            for (int kk = 0; kk < 4; kk++) {
                uint32_t ph[4], pl[4];
                split2(s[2 * kk][0],     s[2 * kk][1],     ph[0], pl[0]);
                split2(s[2 * kk][2],     s[2 * kk][3],     ph[1], pl[1]);
                split2(s[2 * kk + 1][0], s[2 * kk + 1][1], ph[2], pl[2]);
                split2(s[2 * kk + 1][2], s[2 * kk + 1][3], ph[3], pl[3]);
#pragma unroll
                for (int pr = 0; pr < 4; pr++) {
                    const int vrow = kk * 16 + (lane & 7) + (((lane >> 3) & 1) << 3);
                    const int vbc  = pr * 32 + ((lane >> 4) << 4);
                    const uint32_t vo = sw128o(vrow, vbc);
                    uint32_t vh[4], vl[4];
                    LDMX4T(vh, kvb + 2 * 8192 + vo);
                    LDMX4T(vl, kvb + 3 * 8192 + vo);
                    MMA_BF16(o[2 * pr],     ph, vh[0], vh[1]);
                    MMA_BF16(o[2 * pr + 1], ph, vh[2], vh[3]);
                    MMA_BF16(o[2 * pr],     pl, vh[0], vh[1]);
                    MMA_BF16(o[2 * pr + 1], pl, vh[2], vh[3]);
                    MMA_BF16(o[2 * pr],     ph, vl[0], vl[1]);
                    MMA_BF16(o[2 * pr + 1], ph, vl[2], vl[3]);
                }
            }
        }
        __syncthreads();
    }

    // ---- epilogue: C = o / l as bf16 hi/lo, head-interleaved [B,S,D] ----
    const int bi = bh >> 4;
    const int h  = bh & 15;
#pragma unroll
    for (int hf = 0; hf < 2; hf++) {
        const float inv = 1.f / li[hf];
        const int srow = q0 + w * 16 + (lane >> 2) + hf * 8;
#pragma unroll
        for (int nt = 0; nt < 8; nt++) {
            const int col = h * HD + nt * 8 + ((lane & 3) << 1);
            const size_t off = ((size_t)bi * SEQ + srow) * DIM + col;
            uint32_t hi, lo;
            split2(o[nt][2 * hf] * inv, o[nt][2 * hf + 1] * inv, hi, lo);
            *(uint32_t*)&Ch[off] = hi;
            *(uint32_t*)&Cl[off] = lo;
        }
    }
}

// ---------------------------------------------------------------------------
// Launch
// ---------------------------------------------------------------------------
extern "C" void kernel_launch(void* const* d_in, const int* in_sizes, int n_in,
                              void* d_out, int out_size)
{
    (void)in_sizes; (void)n_in; (void)out_size;
    const float* x  = (const float*)d_in[0];
    const float* Wq = (const float*)d_in[2];
    const float* bq = (const float*)d_in[3];
    const float* Wk = (const float*)d_in[4];
    const float* bk = (const float*)d_in[5];
    const float* Wv = (const float*)d_in[6];
    const float* bv = (const float*)d_in[7];
    const float* Wo = (const float*)d_in[8];
    const float* bo = (const float*)d_in[9];
    float* out = (float*)d_out;

    bf16 *Xh, *Xl, *Wh, *Wl, *Qh, *Ql, *Kh, *Kl, *Vh, *Vl, *Ch, *Cl;
    cudaGetSymbolAddress((void**)&Xh, g_Xh);
    cudaGetSymbolAddress((void**)&Xl, g_Xl);
    cudaGetSymbolAddress((void**)&Wh, g_Wh);
    cudaGetSymbolAddress((void**)&Wl, g_Wl);
    cudaGetSymbolAddress((void**)&Qh, g_Qh);
    cudaGetSymbolAddress((void**)&Ql, g_Ql);
    cudaGetSymbolAddress((void**)&Kh, g_Kh);
    cudaGetSymbolAddress((void**)&Kl, g_Kl);
    cudaGetSymbolAddress((void**)&Vh, g_Vh);
    cudaGetSymbolAddress((void**)&Vl, g_Vl);
    cudaGetSymbolAddress((void**)&Ch, g_Ch);
    cudaGetSymbolAddress((void**)&Cl, g_Cl);

    cudaFuncSetAttribute(gemm_mma, cudaFuncAttributeMaxDynamicSharedMemorySize,
                         GSMEM_TOT);
    cudaFuncSetAttribute(flash_mma, cudaFuncAttributeMaxDynamicSharedMemorySize,
                         ASMEM_TOT);

    const size_t WSZ = (size_t)DIM * DIM;

    // Pre-split X and weights to bf16 hi/lo
    split_f32<<<(NR * DIM / 4 + 255) / 256, 256>>>(x, Xh, Xl, NR * DIM / 4);
    split_f32<<<(WSZ / 4 + 255) / 256, 256>>>(Wq, Wh + 0 * WSZ, Wl + 0 * WSZ, WSZ / 4);
    split_f32<<<(WSZ / 4 + 255) / 256, 256>>>(Wk, Wh + 1 * WSZ, Wl + 1 * WSZ, WSZ / 4);
    split_f32<<<(WSZ / 4 + 255) / 256, 256>>>(Wv, Wh + 2 * WSZ, Wl + 2 * WSZ, WSZ / 4);
    split_f32<<<(WSZ / 4 + 255) / 256, 256>>>(Wo, Wh + 3 * WSZ, Wl + 3 * WSZ, WSZ / 4);

    dim3 gemm_grid(DIM / 128, NR / 128);   // 8 x 64
    gemm_mma<<<gemm_grid, 256, GSMEM_TOT>>>(Xh, Xl, Wh + 0 * WSZ, Wl + 0 * WSZ,
                                            bq, nullptr, Qh, Ql, 0);
    gemm_mma<<<gemm_grid, 256, GSMEM_TOT>>>(Xh, Xl, Wh + 1 * WSZ, Wl + 1 * WSZ,
                                            bk, nullptr, Kh, Kl, 0);
    gemm_mma<<<gemm_grid, 256, GSMEM_TOT>>>(Xh, Xl, Wh + 2 * WSZ, Wl + 2 * WSZ,
                                            bv, nullptr, Vh, Vl, 0);

    dim3 attn_grid(SEQ / 128, BATCH * NH);  // 16 x 64
    flash_mma<<<attn_grid, 256, ASMEM_TOT>>>(Qh, Ql, Kh, Kl, Vh, Vl, Ch, Cl);

    gemm_mma<<<gemm_grid, 256, GSMEM_TOT>>>(Ch, Cl, Wh + 3 * WSZ, Wl + 3 * WSZ,
                                            bo, out, nullptr, nullptr, 1);
}

// round 6
// speedup vs baseline: 3.0473x; 1.0514x over previous
#include <cuda_runtime.h>
#include <cuda_bf16.h>
#include <math.h>
#include <stdint.h>

// Problem constants
#define BATCH 4
#define SEQ   2048
#define DIM   1024
#define NH    16
#define HD    64
#define NR    (BATCH * SEQ)        // 8192 rows
#define NRD   ((size_t)NR * DIM)
#define WSZ   ((size_t)DIM * DIM)
#define QK_SCALE 0.125f            // 1/sqrt(64)

typedef __nv_bfloat16 bf16;

// Persistent scratch (allocation-free: __device__ globals)
__device__ bf16 g_Xh[NRD];
__device__ bf16 g_Xl[NRD];
__device__ bf16 g_Wh[4 * WSZ];
__device__ bf16 g_Wl[4 * WSZ];
__device__ bf16 g_QKVh[3 * NRD];   // [B,H,S,HD] each: Q, K, V
__device__ bf16 g_QKVl[3 * NRD];
__device__ bf16 g_Ch[NRD];
__device__ bf16 g_Cl[NRD];

// ===========================================================================
// Helpers
// ===========================================================================
__device__ __forceinline__ uint32_t smem_u32(const void* p) {
    uint32_t a;
    asm("{ .reg .u64 t; cvta.to.shared.u64 t, %1; cvt.u32.u64 %0, t; }"
        : "=r"(a) : "l"(p));
    return a;
}

__device__ __forceinline__ uint32_t pack_bf16x2(float a, float b) {
    __nv_bfloat162 t = __floats2bfloat162_rn(a, b);
    return *reinterpret_cast<uint32_t*>(&t);
}

__device__ __forceinline__ void split2(float a, float b, uint32_t& hi, uint32_t& lo) {
    float h0 = __bfloat162float(__float2bfloat16_rn(a));
    float h1 = __bfloat162float(__float2bfloat16_rn(b));
    hi = pack_bf16x2(h0, h1);
    lo = pack_bf16x2(a - h0, b - h1);
}

#define LDMX4(r, addr) \
    asm volatile("ldmatrix.sync.aligned.m8n8.x4.shared.b16 {%0,%1,%2,%3}, [%4];" \
        : "=r"((r)[0]), "=r"((r)[1]), "=r"((r)[2]), "=r"((r)[3]) : "r"(addr))

#define LDMX4T(r, addr) \
    asm volatile("ldmatrix.sync.aligned.m8n8.x4.trans.shared.b16 {%0,%1,%2,%3}, [%4];" \
        : "=r"((r)[0]), "=r"((r)[1]), "=r"((r)[2]), "=r"((r)[3]) : "r"(addr))

#define MMA_BF16(d, a, b0, b1) \
    asm volatile("mma.sync.aligned.m16n8k16.row.col.f32.bf16.bf16.f32 " \
        "{%0,%1,%2,%3}, {%4,%5,%6,%7}, {%8,%9}, {%0,%1,%2,%3};" \
        : "+f"((d)[0]), "+f"((d)[1]), "+f"((d)[2]), "+f"((d)[3]) \
        : "r"((a)[0]), "r"((a)[1]), "r"((a)[2]), "r"((a)[3]), "r"(b0), "r"(b1))

#define CP_ASYNC16(dst, src) \
    asm volatile("cp.async.cg.shared.global [%0], [%1], 16;" :: "r"(dst), "l"(src))
#define CP_COMMIT() asm volatile("cp.async.commit_group;")
#define CP_WAIT(n)  asm volatile("cp.async.wait_group %0;" :: "n"(n))

// GEMM smem tile: logical [128 rows][32 k bf16], two rows per 128B phys row.
__device__ __forceinline__ uint32_t sw_off(int r, int bytecol) {
    int prow  = r >> 1;
    int chunk = ((r & 1) << 2) | (bytecol >> 4);
    return (uint32_t)(prow * 128 + ((chunk ^ (prow & 7)) << 4) + (bytecol & 15));
}

// Attention smem tile: [rows][64 bf16] = 128B/row, canonical SW128.
__device__ __forceinline__ uint32_t sw128o(int r, int bc) {
    return (uint32_t)(r * 128 + ((((bc >> 4) ^ (r & 7)) << 4)) + (bc & 15));
}

// ===========================================================================
// Pre-split: fp32 -> bf16 hi/lo
// ===========================================================================
__global__ void split_x(const float* __restrict__ in, bf16* __restrict__ hi,
                        bf16* __restrict__ lo)
{
    int i = blockIdx.x * blockDim.x + threadIdx.x;   // over NRD/4 float4s
    float4 v = ((const float4*)in)[i];
    uint2 h, l;
    split2(v.x, v.y, h.x, l.x);
    split2(v.z, v.w, h.y, l.y);
    ((uint2*)hi)[i] = h;
    ((uint2*)lo)[i] = l;
}

__global__ void split_w(const float* __restrict__ w0, const float* __restrict__ w1,
                        const float* __restrict__ w2, const float* __restrict__ w3,
                        bf16* __restrict__ hiB, bf16* __restrict__ loB)
{
    const int z = blockIdx.y;
    const float* in = (z == 0) ? w0 : (z == 1) ? w1 : (z == 2) ? w2 : w3;
    int i = blockIdx.x * blockDim.x + threadIdx.x;   // over WSZ/4 float4s
    float4 v = ((const float4*)in)[i];
    uint2 h, l;
    split2(v.x, v.y, h.x, l.x);
    split2(v.z, v.w, h.y, l.y);
    ((uint2*)(hiB + z * WSZ))[i] = h;
    ((uint2*)(loB + z * WSZ))[i] = l;
}

// ===========================================================================
// Tensor-core GEMM, bf16 hi/lo inputs, cp.async 4-stage, 1 sync/chunk.
// out[n,m] = sum_k A[n,k]*W[m,k] + bias[m]  (bf16x3)
// Tile 128x128, BK=32, 256 threads, warps 4(M) x 2(N).
// mode 0: grid.z selects {W, bias, out} in {Q,K,V}; split-scatter to [B,H,S,DK]
// mode 1: fp32 row-major out
// ===========================================================================
#define GSTG   32768                 // AH,AL,WH,WL tiles of 8KB
#define GSMEM_TOT (4 * GSTG)         // 131072
#define NCH    (DIM / 32)            // 32 chunks

__global__ __launch_bounds__(256, 1)
void gemm_mma(const bf16* __restrict__ Ah, const bf16* __restrict__ Al,
              const bf16* __restrict__ WhB, const bf16* __restrict__ WlB,
              const float* __restrict__ bias0, const float* __restrict__ bias1,
              const float* __restrict__ bias2,
              float* __restrict__ outF,
              bf16* __restrict__ outHB, bf16* __restrict__ outLB, int mode)
{
    extern __shared__ char smem[];
    const uint32_t sb = smem_u32(smem);
    const int tid  = threadIdx.x;
    const int wid  = tid >> 5;
    const int lane = tid & 31;
    const int wm = wid & 3;
    const int wn = wid >> 2;
    const int n0 = blockIdx.y << 7;
    const int m0 = blockIdx.x << 7;
    const int z  = blockIdx.z;

    const bf16* Wh = WhB + (size_t)z * WSZ;
    const bf16* Wl = WlB + (size_t)z * WSZ;
    const float* bias = (z == 0) ? bias0 : (z == 1) ? bias1 : bias2;

    float acc[2][8][4];
#pragma unroll
    for (int mt = 0; mt < 2; mt++)
#pragma unroll
        for (int nt = 0; nt < 8; nt++)
#pragma unroll
            for (int j = 0; j < 4; j++) acc[mt][nt][j] = 0.f;

    auto issue = [&](int c, int stg) {
        const int k0 = c << 5;
        const uint32_t base = sb + stg * GSTG;
#pragma unroll
        for (int i = 0; i < 8; i++) {
            const int idx = (i << 8) + tid;     // 0..2047
            const int arr = idx >> 9;           // 0..3
            const int rem = idx & 511;
            const int row = rem >> 2;           // 0..127
            const int ch  = rem & 3;            // 16B chunk
            const uint32_t dst = base + arr * 8192 + sw_off(row, ch << 4);
            const bf16* g;
            if (arr == 0)      g = Ah + (size_t)(n0 + row) * DIM + k0 + (ch << 3);
            else if (arr == 1) g = Al + (size_t)(n0 + row) * DIM + k0 + (ch << 3);
            else if (arr == 2) g = Wh + (size_t)(m0 + row) * DIM + k0 + (ch << 3);
            else               g = Wl + (size_t)(m0 + row) * DIM + k0 + (ch << 3);
            CP_ASYNC16(dst, g);
        }
        CP_COMMIT();
    };

    auto compute = [&](int stg) {
        const uint32_t buf = sb + stg * GSTG;
#pragma unroll
        for (int ks = 0; ks < 2; ks++) {
            uint32_t a_h[2][4], a_l[2][4], b_h[4][4], b_l[4][4];
#pragma unroll
            for (int mt = 0; mt < 2; mt++) {
                const int r  = wm * 32 + mt * 16 + (lane & 15);
                const int bc = ks * 32 + ((lane >> 4) & 1) * 16;
                const uint32_t o = sw_off(r, bc);
                LDMX4(a_h[mt], buf + 0 * 8192 + o);
                LDMX4(a_l[mt], buf + 1 * 8192 + o);
            }
#pragma unroll
            for (int bt = 0; bt < 4; bt++) {
                const int rn = wn * 64 + bt * 16 + ((lane >> 4) << 3) + (lane & 7);
                const int bc = ks * 32 + ((lane >> 3) & 1) * 16;
                const uint32_t o = sw_off(rn, bc);
                LDMX4(b_h[bt], buf + 2 * 8192 + o);
                LDMX4(b_l[bt], buf + 3 * 8192 + o);
            }
#pragma unroll
            for (int mt = 0; mt < 2; mt++)
#pragma unroll
                for (int nt = 0; nt < 8; nt++)
                    MMA_BF16(acc[mt][nt], a_h[mt],
                             b_h[nt >> 1][(nt & 1) << 1], b_h[nt >> 1][((nt & 1) << 1) + 1]);
#pragma unroll
            for (int mt = 0; mt < 2; mt++)
#pragma unroll
                for (int nt = 0; nt < 8; nt++)
                    MMA_BF16(acc[mt][nt], a_h[mt],
                             b_l[nt >> 1][(nt & 1) << 1], b_l[nt >> 1][((nt & 1) << 1) + 1]);
#pragma unroll
            for (int mt = 0; mt < 2; mt++)
#pragma unroll
                for (int nt = 0; nt < 8; nt++)
                    MMA_BF16(acc[mt][nt], a_l[mt],
                             b_h[nt >> 1][(nt & 1) << 1], b_h[nt >> 1][((nt & 1) << 1) + 1]);
        }
    };

    // 4-stage pipeline, ONE sync per chunk:
    //   wait(c ready) -> sync (also frees buffer (c-1)&3) -> issue c+3 -> compute c
    issue(0, 0); issue(1, 1); issue(2, 2);
    for (int c = 0; c < NCH; c++) {
        if (c + 2 < NCH)      { CP_WAIT(2); }
        else if (c + 1 < NCH) { CP_WAIT(1); }
        else                  { CP_WAIT(0); }
        __syncthreads();
        if (c + 3 < NCH) issue(c + 3, (c + 3) & 3);
        compute(c & 3);
    }

    // Epilogue
#pragma unroll
    for (int mt = 0; mt < 2; mt++) {
        const int r0 = n0 + wm * 32 + mt * 16 + (lane >> 2);
#pragma unroll
        for (int nt = 0; nt < 8; nt++) {
            const int m = m0 + wn * 64 + nt * 8 + ((lane & 3) << 1);
            const float2 bv = *(const float2*)&bias[m];
            float2 v0 = make_float2(acc[mt][nt][0] + bv.x, acc[mt][nt][1] + bv.y);
            float2 v1 = make_float2(acc[mt][nt][2] + bv.x, acc[mt][nt][3] + bv.y);
            if (mode == 0) {
                bf16* outH = outHB + (size_t)z * NRD;
                bf16* outL = outLB + (size_t)z * NRD;
                const int h = m >> 6, dk = m & 63;
                uint32_t hi, lo;
                {
                    const int n = r0, bi = n >> 11, s = n & 2047;
                    const size_t off = (((size_t)bi * NH + h) * SEQ + s) * HD + dk;
                    split2(v0.x, v0.y, hi, lo);
                    *(uint32_t*)&outH[off] = hi;
                    *(uint32_t*)&outL[off] = lo;
                }
                {
                    const int n = r0 + 8, bi = n >> 11, s = n & 2047;
                    const size_t off = (((size_t)bi * NH + h) * SEQ + s) * HD + dk;
                    split2(v1.x, v1.y, hi, lo);
                    *(uint32_t*)&outH[off] = hi;
                    *(uint32_t*)&outL[off] = lo;
                }
            } else {
                *(float2*)&outF[(size_t)r0 * DIM + m] = v0;
                *(float2*)&outF[(size_t)(r0 + 8) * DIM + m] = v1;
            }
        }
    }
}

// ===========================================================================
// Tensor-core causal flash attention, bf16 hi/lo, cp.async 2-stage KV,
// capped at 128 regs for 2 CTAs/SM.
// CTA: 128 q-rows x 64-key tiles. 8 warps, each owns 16 q-rows.
// ===========================================================================
#define AQ_H  0
#define AQ_L  16384
#define AKV0  32768
#define AKVSTG 32768                  // KH,KL,VH,VL tiles of 8KB
#define ASMEM_TOT (AKV0 + 2 * AKVSTG) // 98304

__global__ __launch_bounds__(256, 2)
void flash_mma(const bf16* __restrict__ QKVh, const bf16* __restrict__ QKVl,
               bf16* __restrict__ Ch, bf16* __restrict__ Cl)
{
    extern __shared__ char smem[];
    const uint32_t sb = smem_u32(smem);
    const int tid  = threadIdx.x;
    const int w    = tid >> 5;
    const int lane = tid & 31;
    const int qt = blockIdx.x;
    const int bh = blockIdx.y;
    const int q0 = qt << 7;

    const size_t bhoff = (size_t)bh * SEQ * HD;
    const bf16* Qh = QKVh + bhoff;
    const bf16* Ql = QKVl + bhoff;
    const bf16* Kh = QKVh + NRD + bhoff;
    const bf16* Kl = QKVl + NRD + bhoff;
    const bf16* Vh = QKVh + 2 * NRD + bhoff;
    const bf16* Vl = QKVl + 2 * NRD + bhoff;

    auto issueQ = [&]() {
#pragma unroll
        for (int i = 0; i < 8; i++) {
            const int idx = (i << 8) + tid;    // 0..2047
            const int arr = idx >> 10;         // 0=H, 1=L
            const int rem = idx & 1023;
            const int row = rem >> 3;          // 0..127
            const int ch  = rem & 7;
            const uint32_t dst = sb + (arr ? AQ_L : AQ_H) + sw128o(row, ch << 4);
            const bf16* g = (arr ? Ql : Qh) + (size_t)(q0 + row) * HD + (ch << 3);
            CP_ASYNC16(dst, g);
        }
    };

    auto issueKV = [&](int jt, int b) {
        const size_t k0off = (size_t)(jt << 6) * HD;
        const uint32_t base = sb + AKV0 + b * AKVSTG;
#pragma unroll
        for (int i = 0; i < 8; i++) {
            const int idx = (i << 8) + tid;    // 0..2047
            const int arr = idx >> 9;          // 0:KH 1:KL 2:VH 3:VL
            const int rem = idx & 511;
            const int row = rem >> 3;          // 0..63
            const int ch  = rem & 7;
            const uint32_t dst = base + arr * 8192 + sw128o(row, ch << 4);
            const bf16* g;
            if (arr == 0)      g = Kh + k0off + row * HD + (ch << 3);
            else if (arr == 1) g = Kl + k0off + row * HD + (ch << 3);
            else if (arr == 2) g = Vh + k0off + row * HD + (ch << 3);
            else               g = Vl + k0off + row * HD + (ch << 3);
            CP_ASYNC16(dst, g);
        }
        CP_COMMIT();
    };

    float o[8][4];
    float mx[2], li[2];
#pragma unroll
    for (int nt = 0; nt < 8; nt++)
#pragma unroll
        for (int j = 0; j < 4; j++) o[nt][j] = 0.f;
    mx[0] = mx[1] = -INFINITY;
    li[0] = li[1] = 0.f;

    const int jt_end = 2 * qt + 2;
    const int wrow_max = q0 + w * 16 + 15;

    issueQ();
    issueKV(0, 0);      // Q + KV0 in group 0

    for (int jt = 0; jt < jt_end; jt++) {
        const int k0 = jt << 6;
        if (jt + 1 < jt_end) {
            issueKV(jt + 1, (jt + 1) & 1);
            CP_WAIT(1);
        } else {
            CP_WAIT(0);
        }
        __syncthreads();

        if (k0 <= wrow_max) {
            const uint32_t kvb = sb + AKV0 + (jt & 1) * AKVSTG;

            // ---- S = Q K^T (bf16x3) ----
            float s[8][4];
#pragma unroll
            for (int nt = 0; nt < 8; nt++)
#pragma unroll
                for (int j = 0; j < 4; j++) s[nt][j] = 0.f;

#pragma unroll
            for (int ks = 0; ks < 4; ks++) {
                uint32_t qh[4], ql[4];
                const uint32_t qo = sw128o(w * 16 + (lane & 15),
                                           ks * 32 + ((lane >> 4) & 1) * 16);
                LDMX4(qh, sb + AQ_H + qo);
                LDMX4(ql, sb + AQ_L + qo);
#pragma unroll
                for (int bt = 0; bt < 4; bt++) {
                    const int rn = bt * 16 + ((lane >> 4) << 3) + (lane & 7);
                    const int bc = ks * 32 + ((lane >> 3) & 1) * 16;
                    const uint32_t ko = sw128o(rn, bc);
                    uint32_t kh[4], kl[4];
                    LDMX4(kh, kvb + 0 * 8192 + ko);
                    LDMX4(kl, kvb + 1 * 8192 + ko);
                    MMA_BF16(s[2 * bt],     qh, kh[0], kh[1]);
                    MMA_BF16(s[2 * bt + 1], qh, kh[2], kh[3]);
                    MMA_BF16(s[2 * bt],     qh, kl[0], kl[1]);
                    MMA_BF16(s[2 * bt + 1], qh, kl[2], kl[3]);
                    MMA_BF16(s[2 * bt],     ql, kh[0], kh[1]);
                    MMA_BF16(s[2 * bt + 1], ql, kh[2], kh[3]);
                }
            }

            // ---- scale + causal mask ----
            const int r0g = q0 + w * 16 + (lane >> 2);
            const bool diag = (jt >= 2 * qt);
#pragma unroll
            for (int nt = 0; nt < 8; nt++)
#pragma unroll
                for (int j = 0; j < 4; j++) {
                    float v = s[nt][j] * QK_SCALE;
                    if (diag) {
                        const int col = k0 + nt * 8 + ((lane & 3) << 1) + (j & 1);
                        const int row = r0g + ((j >> 1) << 3);
                        if (col > row) v = -INFINITY;
                    }
                    s[nt][j] = v;
                }

            // ---- online softmax ----
#pragma unroll
            for (int hf = 0; hf < 2; hf++) {
                float rm = -INFINITY;
#pragma unroll
                for (int nt = 0; nt < 8; nt++)
                    rm = fmaxf(rm, fmaxf(s[nt][2 * hf], s[nt][2 * hf + 1]));
                rm = fmaxf(rm, __shfl_xor_sync(0xffffffffu, rm, 1));
                rm = fmaxf(rm, __shfl_xor_sync(0xffffffffu, rm, 2));
                const float mn = fmaxf(mx[hf], rm);
                const float al = __expf(mx[hf] - mn);
                mx[hf] = mn;
                float rs = 0.f;
#pragma unroll
                for (int nt = 0; nt < 8; nt++) {
                    float e0 = __expf(s[nt][2 * hf] - mn);
                    float e1 = __expf(s[nt][2 * hf + 1] - mn);
                    s[nt][2 * hf] = e0; s[nt][2 * hf + 1] = e1;
                    rs += e0 + e1;
                }
                rs += __shfl_xor_sync(0xffffffffu, rs, 1);
                rs += __shfl_xor_sync(0xffffffffu, rs, 2);
                li[hf] = li[hf] * al + rs;
#pragma unroll
                for (int nt = 0; nt < 8; nt++) {
                    o[nt][2 * hf]     *= al;
                    o[nt][2 * hf + 1] *= al;
                }
            }

            // ---- O += P V (bf16x3) ----
#pragma unroll
            for (int kk = 0; kk < 4; kk++) {
                uint32_t ph[4], pl[4];
                split2(s[2 * kk][0],     s[2 * kk][1],     ph[0], pl[0]);
                split2(s[2 * kk][2],     s[2 * kk][3],     ph[1], pl[1]);
                split2(s[2 * kk + 1][0], s[2 * kk + 1][1], ph[2], pl[2]);
                split2(s[2 * kk + 1][2], s[2 * kk + 1][3], ph[3], pl[3]);
#pragma unroll
                for (int pr = 0; pr < 4; pr++) {
                    const int vrow = kk * 16 + (lane & 7) + (((lane >> 3) & 1) << 3);
                    const int vbc  = pr * 32 + ((lane >> 4) << 4);
                    const uint32_t vo = sw128o(vrow, vbc);
                    uint32_t vh[4], vl[4];
                    LDMX4T(vh, kvb + 2 * 8192 + vo);
                    LDMX4T(vl, kvb + 3 * 8192 + vo);
                    MMA_BF16(o[2 * pr],     ph, vh[0], vh[1]);
                    MMA_BF16(o[2 * pr + 1], ph, vh[2], vh[3]);
                    MMA_BF16(o[2 * pr],     pl, vh[0], vh[1]);
                    MMA_BF16(o[2 * pr + 1], pl, vh[2], vh[3]);
                    MMA_BF16(o[2 * pr],     ph, vl[0], vl[1]);
                    MMA_BF16(o[2 * pr + 1], ph, vl[2], vl[3]);
                }
            }
        }
        __syncthreads();
    }

    // ---- epilogue: C = o / l as bf16 hi/lo, head-interleaved [B,S,D] ----
    const int bi = bh >> 4;
    const int h  = bh & 15;
#pragma unroll
    for (int hf = 0; hf < 2; hf++) {
        const float inv = 1.f / li[hf];
        const int srow = q0 + w * 16 + (lane >> 2) + hf * 8;
#pragma unroll
        for (int nt = 0; nt < 8; nt++) {
            const int col = h * HD + nt * 8 + ((lane & 3) << 1);
            const size_t off = ((size_t)bi * SEQ + srow) * DIM + col;
            uint32_t hi, lo;
            split2(o[nt][2 * hf] * inv, o[nt][2 * hf + 1] * inv, hi, lo);
            *(uint32_t*)&Ch[off] = hi;
            *(uint32_t*)&Cl[off] = lo;
        }
    }
}

// ---------------------------------------------------------------------------
// Launch
// ---------------------------------------------------------------------------
extern "C" void kernel_launch(void* const* d_in, const int* in_sizes, int n_in,
                              void* d_out, int out_size)
{
    (void)in_sizes; (void)n_in; (void)out_size;
    const float* x  = (const float*)d_in[0];
    const float* Wq = (const float*)d_in[2];
    const float* bq = (const float*)d_in[3];
    const float* Wk = (const float*)d_in[4];
    const float* bk = (const float*)d_in[5];
    const float* Wv = (const float*)d_in[6];
    const float* bv = (const float*)d_in[7];
    const float* Wo = (const float*)d_in[8];
    const float* bo = (const float*)d_in[9];
    float* out = (float*)d_out;

    bf16 *Xh, *Xl, *Wh, *Wl, *QKVh, *QKVl, *Ch, *Cl;
    cudaGetSymbolAddress((void**)&Xh, g_Xh);
    cudaGetSymbolAddress((void**)&Xl, g_Xl);
    cudaGetSymbolAddress((void**)&Wh, g_Wh);
    cudaGetSymbolAddress((void**)&Wl, g_Wl);
    cudaGetSymbolAddress((void**)&QKVh, g_QKVh);
    cudaGetSymbolAddress((void**)&QKVl, g_QKVl);
    cudaGetSymbolAddress((void**)&Ch, g_Ch);
    cudaGetSymbolAddress((void**)&Cl, g_Cl);

    cudaFuncSetAttribute(gemm_mma, cudaFuncAttributeMaxDynamicSharedMemorySize,
                         GSMEM_TOT);
    cudaFuncSetAttribute(flash_mma, cudaFuncAttributeMaxDynamicSharedMemorySize,
                         ASMEM_TOT);

    // Pre-split X and weights to bf16 hi/lo
    split_x<<<NRD / 4 / 256, 256>>>(x, Xh, Xl);
    dim3 wgrid(WSZ / 4 / 256, 4);
    split_w<<<wgrid, 256>>>(Wq, Wk, Wv, Wo, Wh, Wl);

    // Fused QKV projection (grid.z = 3 selects weight/bias/output)
    dim3 qkv_grid(DIM / 128, NR / 128, 3);
    gemm_mma<<<qkv_grid, 256, GSMEM_TOT>>>(Xh, Xl, Wh, Wl, bq, bk, bv,
                                           nullptr, QKVh, QKVl, 0);

    dim3 attn_grid(SEQ / 128, BATCH * NH);  // 16 x 64
    flash_mma<<<attn_grid, 256, ASMEM_TOT>>>(QKVh, QKVl, Ch, Cl);

    // Output projection (weight slot 3)
    dim3 o_grid(DIM / 128, NR / 128, 1);
    gemm_mma<<<o_grid, 256, GSMEM_TOT>>>(Ch, Cl, Wh + 3 * WSZ, Wl + 3 * WSZ,
                                         bo, bo, bo, out, nullptr, nullptr, 1);
}

// round 7
// speedup vs baseline: 3.2145x; 1.0549x over previous
#include <cuda_runtime.h>
#include <cuda_bf16.h>
#include <math.h>
#include <stdint.h>

// Problem constants
#define BATCH 4
#define SEQ   2048
#define DIM   1024
#define NH    16
#define HD    64
#define NR    (BATCH * SEQ)        // 8192 rows
#define NRD   ((size_t)NR * DIM)
#define WSZ   ((size_t)DIM * DIM)
#define QK_SCALE 0.125f            // 1/sqrt(64)

typedef __nv_bfloat16 bf16;

// Persistent scratch (allocation-free: __device__ globals)
__device__ bf16 g_Xh[NRD];
__device__ bf16 g_Xl[NRD];
__device__ bf16 g_Wh[4 * WSZ];
__device__ bf16 g_Wl[4 * WSZ];
__device__ bf16 g_QKVh[3 * NRD];   // [B,H,S,HD] each: Q, K, V
__device__ bf16 g_QKVl[3 * NRD];
__device__ bf16 g_Ch[NRD];
__device__ bf16 g_Cl[NRD];

// ===========================================================================
// Helpers
// ===========================================================================
__device__ __forceinline__ uint32_t smem_u32(const void* p) {
    uint32_t a;
    asm("{ .reg .u64 t; cvta.to.shared.u64 t, %1; cvt.u32.u64 %0, t; }"
        : "=r"(a) : "l"(p));
    return a;
}

__device__ __forceinline__ uint32_t pack_bf16x2(float a, float b) {
    __nv_bfloat162 t = __floats2bfloat162_rn(a, b);
    return *reinterpret_cast<uint32_t*>(&t);
}

__device__ __forceinline__ void split2(float a, float b, uint32_t& hi, uint32_t& lo) {
    float h0 = __bfloat162float(__float2bfloat16_rn(a));
    float h1 = __bfloat162float(__float2bfloat16_rn(b));
    hi = pack_bf16x2(h0, h1);
    lo = pack_bf16x2(a - h0, b - h1);
}

#define LDMX4(r, addr) \
    asm volatile("ldmatrix.sync.aligned.m8n8.x4.shared.b16 {%0,%1,%2,%3}, [%4];" \
        : "=r"((r)[0]), "=r"((r)[1]), "=r"((r)[2]), "=r"((r)[3]) : "r"(addr))

#define LDMX4T(r, addr) \
    asm volatile("ldmatrix.sync.aligned.m8n8.x4.trans.shared.b16 {%0,%1,%2,%3}, [%4];" \
        : "=r"((r)[0]), "=r"((r)[1]), "=r"((r)[2]), "=r"((r)[3]) : "r"(addr))

#define MMA_BF16(d, a, b0, b1) \
    asm volatile("mma.sync.aligned.m16n8k16.row.col.f32.bf16.bf16.f32 " \
        "{%0,%1,%2,%3}, {%4,%5,%6,%7}, {%8,%9}, {%0,%1,%2,%3};" \
        : "+f"((d)[0]), "+f"((d)[1]), "+f"((d)[2]), "+f"((d)[3]) \
        : "r"((a)[0]), "r"((a)[1]), "r"((a)[2]), "r"((a)[3]), "r"(b0), "r"(b1))

#define CP_ASYNC16(dst, src) \
    asm volatile("cp.async.cg.shared.global [%0], [%1], 16;" :: "r"(dst), "l"(src))
#define CP_COMMIT() asm volatile("cp.async.commit_group;")
#define CP_WAIT(n)  asm volatile("cp.async.wait_group %0;" :: "n"(n))

// GEMM smem tile: logical [rows][32 k bf16], two rows per 128B phys row.
__device__ __forceinline__ uint32_t sw_off(int r, int bytecol) {
    int prow  = r >> 1;
    int chunk = ((r & 1) << 2) | (bytecol >> 4);
    return (uint32_t)(prow * 128 + ((chunk ^ (prow & 7)) << 4) + (bytecol & 15));
}

// Attention smem tile: [rows][64 bf16] = 128B/row, canonical SW128.
__device__ __forceinline__ uint32_t sw128o(int r, int bc) {
    return (uint32_t)(r * 128 + ((((bc >> 4) ^ (r & 7)) << 4)) + (bc & 15));
}

// ===========================================================================
// Pre-split: fp32 -> bf16 hi/lo
// ===========================================================================
__global__ void split_x(const float* __restrict__ in, bf16* __restrict__ hi,
                        bf16* __restrict__ lo)
{
    int i = blockIdx.x * blockDim.x + threadIdx.x;
    float4 v = ((const float4*)in)[i];
    uint2 h, l;
    split2(v.x, v.y, h.x, l.x);
    split2(v.z, v.w, h.y, l.y);
    ((uint2*)hi)[i] = h;
    ((uint2*)lo)[i] = l;
}

__global__ void split_w(const float* __restrict__ w0, const float* __restrict__ w1,
                        const float* __restrict__ w2, const float* __restrict__ w3,
                        bf16* __restrict__ hiB, bf16* __restrict__ loB)
{
    const int z = blockIdx.y;
    const float* in = (z == 0) ? w0 : (z == 1) ? w1 : (z == 2) ? w2 : w3;
    int i = blockIdx.x * blockDim.x + threadIdx.x;
    float4 v = ((const float4*)in)[i];
    uint2 h, l;
    split2(v.x, v.y, h.x, l.x);
    split2(v.z, v.w, h.y, l.y);
    ((uint2*)(hiB + z * WSZ))[i] = h;
    ((uint2*)(loB + z * WSZ))[i] = l;
}

// ===========================================================================
// Tensor-core GEMM, bf16 hi/lo inputs, cp.async 3-stage.
// CTA tile 256(A-rows) x 128(W-rows), BK=32. 8 warps = 4(M) x 2(N),
// warp tile 64x64 (smem:tensor ~1.3:1 instead of 2.6:1).
// mode 0: grid.z selects {W, bias, out} in {Q,K,V}; split-scatter to [B,H,S,DK]
// mode 1: fp32 row-major out
// ===========================================================================
#define GA_H   0
#define GA_L   16384
#define GB_H   32768
#define GB_L   40960
#define GSTG   49152                 // one stage: Ah16K Al16K Bh8K Bl8K
#define GSMEM_TOT (3 * GSTG)         // 147456
#define NCH    (DIM / 32)            // 32 chunks

__global__ __launch_bounds__(256, 1)
void gemm_mma(const bf16* __restrict__ Ah, const bf16* __restrict__ Al,
              const bf16* __restrict__ WhB, const bf16* __restrict__ WlB,
              const float* __restrict__ bias0, const float* __restrict__ bias1,
              const float* __restrict__ bias2,
              float* __restrict__ outF,
              bf16* __restrict__ outHB, bf16* __restrict__ outLB, int mode)
{
    extern __shared__ char smem[];
    const uint32_t sb = smem_u32(smem);
    const int tid  = threadIdx.x;
    const int wid  = tid >> 5;
    const int lane = tid & 31;
    const int wm = wid & 3;          // 4 M-warps (64 rows each)
    const int wn = wid >> 2;         // 2 N-warps (64 cols each)
    const int n0 = blockIdx.y << 8;  // 256 A-rows per CTA
    const int m0 = blockIdx.x << 7;  // 128 W-rows per CTA
    const int z  = blockIdx.z;

    const bf16* Wh = WhB + (size_t)z * WSZ;
    const bf16* Wl = WlB + (size_t)z * WSZ;
    const float* bias = (z == 0) ? bias0 : (z == 1) ? bias1 : bias2;

    float acc[4][8][4];
#pragma unroll
    for (int mt = 0; mt < 4; mt++)
#pragma unroll
        for (int nt = 0; nt < 8; nt++)
#pragma unroll
            for (int j = 0; j < 4; j++) acc[mt][nt][j] = 0.f;

    auto issue = [&](int c, int stg) {
        const int k0 = c << 5;
        const uint32_t base = sb + stg * GSTG;
#pragma unroll
        for (int i = 0; i < 12; i++) {
            const int idx = (i << 8) + tid;     // 0..3071 16B-chunks
            int arr, ci;
            if (idx < 1024)      { arr = 0; ci = idx; }
            else if (idx < 2048) { arr = 1; ci = idx - 1024; }
            else if (idx < 2560) { arr = 2; ci = idx - 2048; }
            else                 { arr = 3; ci = idx - 2560; }
            const int row = ci >> 2;
            const int ch  = ci & 3;
            const uint32_t aoff = (arr == 0) ? GA_H : (arr == 1) ? GA_L
                                : (arr == 2) ? GB_H : GB_L;
            const uint32_t dst = base + aoff + sw_off(row, ch << 4);
            const bf16* g;
            if (arr == 0)      g = Ah + (size_t)(n0 + row) * DIM + k0 + (ch << 3);
            else if (arr == 1) g = Al + (size_t)(n0 + row) * DIM + k0 + (ch << 3);
            else if (arr == 2) g = Wh + (size_t)(m0 + row) * DIM + k0 + (ch << 3);
            else               g = Wl + (size_t)(m0 + row) * DIM + k0 + (ch << 3);
            CP_ASYNC16(dst, g);
        }
        CP_COMMIT();
    };

    auto compute = [&](int stg) {
        const uint32_t buf = sb + stg * GSTG;
#pragma unroll
        for (int ks = 0; ks < 2; ks++) {
            uint32_t a_h[4][4], a_l[4][4];
#pragma unroll
            for (int mt = 0; mt < 4; mt++) {
                const int r  = wm * 64 + mt * 16 + (lane & 15);
                const int bc = ks * 32 + ((lane >> 4) & 1) * 16;
                const uint32_t o = sw_off(r, bc);
                LDMX4(a_h[mt], buf + GA_H + o);
                LDMX4(a_l[mt], buf + GA_L + o);
            }
#pragma unroll
            for (int bt = 0; bt < 4; bt++) {       // B loaded per-bt: caps liveness
                const int rn = wn * 64 + bt * 16 + ((lane >> 4) << 3) + (lane & 7);
                const int bc = ks * 32 + ((lane >> 3) & 1) * 16;
                const uint32_t o = sw_off(rn, bc);
                uint32_t b_h[4], b_l[4];
                LDMX4(b_h, buf + GB_H + o);
                LDMX4(b_l, buf + GB_L + o);
#pragma unroll
                for (int mt = 0; mt < 4; mt++) {
                    MMA_BF16(acc[mt][2 * bt],     a_h[mt], b_h[0], b_h[1]);
                    MMA_BF16(acc[mt][2 * bt + 1], a_h[mt], b_h[2], b_h[3]);
                    MMA_BF16(acc[mt][2 * bt],     a_h[mt], b_l[0], b_l[1]);
                    MMA_BF16(acc[mt][2 * bt + 1], a_h[mt], b_l[2], b_l[3]);
                    MMA_BF16(acc[mt][2 * bt],     a_l[mt], b_h[0], b_h[1]);
                    MMA_BF16(acc[mt][2 * bt + 1], a_l[mt], b_h[2], b_h[3]);
                }
            }
        }
    };

    // 3-stage pipeline, one sync per chunk
    issue(0, 0); issue(1, 1);
    for (int c = 0; c < NCH; c++) {
        if (c + 1 < NCH) { CP_WAIT(1); }
        else             { CP_WAIT(0); }
        __syncthreads();
        if (c + 2 < NCH) {
            int s = c + 2; while (s >= 3) s -= 3;
            issue(c + 2, s);
        }
        int cs = c; while (cs >= 3) cs -= 3;
        compute(cs);
    }

    // Epilogue
#pragma unroll
    for (int mt = 0; mt < 4; mt++) {
        const int r0 = n0 + wm * 64 + mt * 16 + (lane >> 2);
#pragma unroll
        for (int nt = 0; nt < 8; nt++) {
            const int m = m0 + wn * 64 + nt * 8 + ((lane & 3) << 1);
            const float2 bv = *(const float2*)&bias[m];
            float2 v0 = make_float2(acc[mt][nt][0] + bv.x, acc[mt][nt][1] + bv.y);
            float2 v1 = make_float2(acc[mt][nt][2] + bv.x, acc[mt][nt][3] + bv.y);
            if (mode == 0) {
                bf16* outH = outHB + (size_t)z * NRD;
                bf16* outL = outLB + (size_t)z * NRD;
                const int h = m >> 6, dk = m & 63;
                uint32_t hi, lo;
                {
                    const int n = r0, bi = n >> 11, s = n & 2047;
                    const size_t off = (((size_t)bi * NH + h) * SEQ + s) * HD + dk;
                    split2(v0.x, v0.y, hi, lo);
                    *(uint32_t*)&outH[off] = hi;
                    *(uint32_t*)&outL[off] = lo;
                }
                {
                    const int n = r0 + 8, bi = n >> 11, s = n & 2047;
                    const size_t off = (((size_t)bi * NH + h) * SEQ + s) * HD + dk;
                    split2(v1.x, v1.y, hi, lo);
                    *(uint32_t*)&outH[off] = hi;
                    *(uint32_t*)&outL[off] = lo;
                }
            } else {
                *(float2*)&outF[(size_t)r0 * DIM + m] = v0;
                *(float2*)&outF[(size_t)(r0 + 8) * DIM + m] = v1;
            }
        }
    }
}

// ===========================================================================
// Tensor-core causal flash attention (unchanged from R6).
// ===========================================================================
#define AQ_H  0
#define AQ_L  16384
#define AKV0  32768
#define AKVSTG 32768
#define ASMEM_TOT (AKV0 + 2 * AKVSTG) // 98304

__global__ __launch_bounds__(256, 2)
void flash_mma(const bf16* __restrict__ QKVh, const bf16* __restrict__ QKVl,
               bf16* __restrict__ Ch, bf16* __restrict__ Cl)
{
    extern __shared__ char smem[];
    const uint32_t sb = smem_u32(smem);
    const int tid  = threadIdx.x;
    const int w    = tid >> 5;
    const int lane = tid & 31;
    const int qt = blockIdx.x;
    const int bh = blockIdx.y;
    const int q0 = qt << 7;

    const size_t bhoff = (size_t)bh * SEQ * HD;
    const bf16* Qh = QKVh + bhoff;
    const bf16* Ql = QKVl + bhoff;
    const bf16* Kh = QKVh + NRD + bhoff;
    const bf16* Kl = QKVl + NRD + bhoff;
    const bf16* Vh = QKVh + 2 * NRD + bhoff;
    const bf16* Vl = QKVl + 2 * NRD + bhoff;

    auto issueQ = [&]() {
#pragma unroll
        for (int i = 0; i < 8; i++) {
            const int idx = (i << 8) + tid;
            const int arr = idx >> 10;
            const int rem = idx & 1023;
            const int row = rem >> 3;
            const int ch  = rem & 7;
            const uint32_t dst = sb + (arr ? AQ_L : AQ_H) + sw128o(row, ch << 4);
            const bf16* g = (arr ? Ql : Qh) + (size_t)(q0 + row) * HD + (ch << 3);
            CP_ASYNC16(dst, g);
        }
    };

    auto issueKV = [&](int jt, int b) {
        const size_t k0off = (size_t)(jt << 6) * HD;
        const uint32_t base = sb + AKV0 + b * AKVSTG;
#pragma unroll
        for (int i = 0; i < 8; i++) {
            const int idx = (i << 8) + tid;
            const int arr = idx >> 9;
            const int rem = idx & 511;
            const int row = rem >> 3;
            const int ch  = rem & 7;
            const uint32_t dst = base + arr * 8192 + sw128o(row, ch << 4);
            const bf16* g;
            if (arr == 0)      g = Kh + k0off + row * HD + (ch << 3);
            else if (arr == 1) g = Kl + k0off + row * HD + (ch << 3);
            else if (arr == 2) g = Vh + k0off + row * HD + (ch << 3);
            else               g = Vl + k0off + row * HD + (ch << 3);
            CP_ASYNC16(dst, g);
        }
        CP_COMMIT();
    };

    float o[8][4];
    float mx[2], li[2];
#pragma unroll
    for (int nt = 0; nt < 8; nt++)
#pragma unroll
        for (int j = 0; j < 4; j++) o[nt][j] = 0.f;
    mx[0] = mx[1] = -INFINITY;
    li[0] = li[1] = 0.f;

    const int jt_end = 2 * qt + 2;
    const int wrow_max = q0 + w * 16 + 15;

    issueQ();
    issueKV(0, 0);

    for (int jt = 0; jt < jt_end; jt++) {
        const int k0 = jt << 6;
        if (jt + 1 < jt_end) {
            issueKV(jt + 1, (jt + 1) & 1);
            CP_WAIT(1);
        } else {
            CP_WAIT(0);
        }
        __syncthreads();

        if (k0 <= wrow_max) {
            const uint32_t kvb = sb + AKV0 + (jt & 1) * AKVSTG;

            float s[8][4];
#pragma unroll
            for (int nt = 0; nt < 8; nt++)
#pragma unroll
                for (int j = 0; j < 4; j++) s[nt][j] = 0.f;

#pragma unroll
            for (int ks = 0; ks < 4; ks++) {
                uint32_t qh[4], ql[4];
                const uint32_t qo = sw128o(w * 16 + (lane & 15),
                                           ks * 32 + ((lane >> 4) & 1) * 16);
                LDMX4(qh, sb + AQ_H + qo);
                LDMX4(ql, sb + AQ_L + qo);
#pragma unroll
                for (int bt = 0; bt < 4; bt++) {
                    const int rn = bt * 16 + ((lane >> 4) << 3) + (lane & 7);
                    const int bc = ks * 32 + ((lane >> 3) & 1) * 16;
                    const uint32_t ko = sw128o(rn, bc);
                    uint32_t kh[4], kl[4];
                    LDMX4(kh, kvb + 0 * 8192 + ko);
                    LDMX4(kl, kvb + 1 * 8192 + ko);
                    MMA_BF16(s[2 * bt],     qh, kh[0], kh[1]);
                    MMA_BF16(s[2 * bt + 1], qh, kh[2], kh[3]);
                    MMA_BF16(s[2 * bt],     qh, kl[0], kl[1]);
                    MMA_BF16(s[2 * bt + 1], qh, kl[2], kl[3]);
                    MMA_BF16(s[2 * bt],     ql, kh[0], kh[1]);
                    MMA_BF16(s[2 * bt + 1], ql, kh[2], kh[3]);
                }
            }

            const int r0g = q0 + w * 16 + (lane >> 2);
            const bool diag = (jt >= 2 * qt);
#pragma unroll
            for (int nt = 0; nt < 8; nt++)
#pragma unroll
                for (int j = 0; j < 4; j++) {
                    float v = s[nt][j] * QK_SCALE;
                    if (diag) {
                        const int col = k0 + nt * 8 + ((lane & 3) << 1) + (j & 1);
                        const int row = r0g + ((j >> 1) << 3);
                        if (col > row) v = -INFINITY;
                    }
                    s[nt][j] = v;
                }

#pragma unroll
            for (int hf = 0; hf < 2; hf++) {
                float rm = -INFINITY;
#pragma unroll
                for (int nt = 0; nt < 8; nt++)
                    rm = fmaxf(rm, fmaxf(s[nt][2 * hf], s[nt][2 * hf + 1]));
                rm = fmaxf(rm, __shfl_xor_sync(0xffffffffu, rm, 1));
                rm = fmaxf(rm, __shfl_xor_sync(0xffffffffu, rm, 2));
                const float mn = fmaxf(mx[hf], rm);
                const float al = __expf(mx[hf] - mn);
                mx[hf] = mn;
                float rs = 0.f;
#pragma unroll
                for (int nt = 0; nt < 8; nt++) {
                    float e0 = __expf(s[nt][2 * hf] - mn);
                    float e1 = __expf(s[nt][2 * hf + 1] - mn);
                    s[nt][2 * hf] = e0; s[nt][2 * hf + 1] = e1;
                    rs += e0 + e1;
                }
                rs += __shfl_xor_sync(0xffffffffu, rs, 1);
                rs += __shfl_xor_sync(0xffffffffu, rs, 2);
                li[hf] = li[hf] * al + rs;
#pragma unroll
                for (int nt = 0; nt < 8; nt++) {
                    o[nt][2 * hf]     *= al;
                    o[nt][2 * hf + 1] *= al;
                }
            }

#pragma unroll
            for (int kk = 0; kk < 4; kk++) {
                uint32_t ph[4], pl[4];
                split2(s[2 * kk][0],     s[2 * kk][1],     ph[0], pl[0]);
                split2(s[2 * kk][2],     s[2 * kk][3],     ph[1], pl[1]);
                split2(s[2 * kk + 1][0], s[2 * kk + 1][1], ph[2], pl[2]);
                split2(s[2 * kk + 1][2], s[2 * kk + 1][3], ph[3], pl[3]);
#pragma unroll
                for (int pr = 0; pr < 4; pr++) {
                    const int vrow = kk * 16 + (lane & 7) + (((lane >> 3) & 1) << 3);
                    const int vbc  = pr * 32 + ((lane >> 4) << 4);
                    const uint32_t vo = sw128o(vrow, vbc);
                    uint32_t vh[4], vl[4];
                    LDMX4T(vh, kvb + 2 * 8192 + vo);
                    LDMX4T(vl, kvb + 3 * 8192 + vo);
                    MMA_BF16(o[2 * pr],     ph, vh[0], vh[1]);
                    MMA_BF16(o[2 * pr + 1], ph, vh[2], vh[3]);
                    MMA_BF16(o[2 * pr],     pl, vh[0], vh[1]);
                    MMA_BF16(o[2 * pr + 1], pl, vh[2], vh[3]);
                    MMA_BF16(o[2 * pr],     ph, vl[0], vl[1]);
                    MMA_BF16(o[2 * pr + 1], ph, vl[2], vl[3]);
                }
            }
        }
        __syncthreads();
    }

    const int bi = bh >> 4;
    const int h  = bh & 15;
#pragma unroll
    for (int hf = 0; hf < 2; hf++) {
        const float inv = 1.f / li[hf];
        const int srow = q0 + w * 16 + (lane >> 2) + hf * 8;
#pragma unroll
        for (int nt = 0; nt < 8; nt++) {
            const int col = h * HD + nt * 8 + ((lane & 3) << 1);
            const size_t off = ((size_t)bi * SEQ + srow) * DIM + col;
            uint32_t hi, lo;
            split2(o[nt][2 * hf] * inv, o[nt][2 * hf + 1] * inv, hi, lo);
            *(uint32_t*)&Ch[off] = hi;
            *(uint32_t*)&Cl[off] = lo;
        }
    }
}

// ---------------------------------------------------------------------------
// Launch
// ---------------------------------------------------------------------------
extern "C" void kernel_launch(void* const* d_in, const int* in_sizes, int n_in,
                              void* d_out, int out_size)
{
    (void)in_sizes; (void)n_in; (void)out_size;
    const float* x  = (const float*)d_in[0];
    const float* Wq = (const float*)d_in[2];
    const float* bq = (const float*)d_in[3];
    const float* Wk = (const float*)d_in[4];
    const float* bk = (const float*)d_in[5];
    const float* Wv = (const float*)d_in[6];
    const float* bv = (const float*)d_in[7];
    const float* Wo = (const float*)d_in[8];
    const float* bo = (const float*)d_in[9];
    float* out = (float*)d_out;

    bf16 *Xh, *Xl, *Wh, *Wl, *QKVh, *QKVl, *Ch, *Cl;
    cudaGetSymbolAddress((void**)&Xh, g_Xh);
    cudaGetSymbolAddress((void**)&Xl, g_Xl);
    cudaGetSymbolAddress((void**)&Wh, g_Wh);
    cudaGetSymbolAddress((void**)&Wl, g_Wl);
    cudaGetSymbolAddress((void**)&QKVh, g_QKVh);
    cudaGetSymbolAddress((void**)&QKVl, g_QKVl);
    cudaGetSymbolAddress((void**)&Ch, g_Ch);
    cudaGetSymbolAddress((void**)&Cl, g_Cl);

    cudaFuncSetAttribute(gemm_mma, cudaFuncAttributeMaxDynamicSharedMemorySize,
                         GSMEM_TOT);
    cudaFuncSetAttribute(flash_mma, cudaFuncAttributeMaxDynamicSharedMemorySize,
                         ASMEM_TOT);

    // Pre-split X and weights to bf16 hi/lo
    split_x<<<NRD / 4 / 256, 256>>>(x, Xh, Xl);
    dim3 wgrid(WSZ / 4 / 256, 4);
    split_w<<<wgrid, 256>>>(Wq, Wk, Wv, Wo, Wh, Wl);

    // Fused QKV projection (grid.z = 3 selects weight/bias/output)
    dim3 qkv_grid(DIM / 128, NR / 256, 3);
    gemm_mma<<<qkv_grid, 256, GSMEM_TOT>>>(Xh, Xl, Wh, Wl, bq, bk, bv,
                                           nullptr, QKVh, QKVl, 0);

    dim3 attn_grid(SEQ / 128, BATCH * NH);  // 16 x 64
    flash_mma<<<attn_grid, 256, ASMEM_TOT>>>(QKVh, QKVl, Ch, Cl);

    // Output projection (weight slot 3)
    dim3 o_grid(DIM / 128, NR / 256, 1);
    gemm_mma<<<o_grid, 256, GSMEM_TOT>>>(Ch, Cl, Wh + 3 * WSZ, Wl + 3 * WSZ,
                                         bo, bo, bo, out, nullptr, nullptr, 1);
}